// round 3
// baseline (speedup 1.0000x reference)
#include <cuda_runtime.h>
#include <cuda_bf16.h>

// Problem constants:
//   input   [64, 32, 32, 16, 16] f32   (B, CLN, QL, IH, IW)
//   context [64, 256, 128]       f32   (B, CDF, SL)
//   W       [8192, 256]          f32   (IDF, CDF)
// Outputs (concatenated in d_out):
//   wc    [64, 32, 32, 16, 16] f32  -> 16,777,216 elems
//   attnT [64, 128, 32]        f32  ->    262,144 elems

#define B_SZ   64
#define QL_SZ  32
#define CDF_SZ 256
#define SL_SZ  128
#define IDF_SZ 8192
#define WC_ELEMS (B_SZ * IDF_SZ * QL_SZ)   // 16777216
#define KSPLIT 16
#define T2_STRIDE (B_SZ * QL_SZ * CDF_SZ)  // 524288 floats per k-split partial

// Scratch (device globals; no allocation allowed)
__device__ float g_T2p[KSPLIT * T2_STRIDE];     // [ks][b][q][c]  32 MB
__device__ float g_CA[B_SZ * CDF_SZ * QL_SZ];   // [b][c][q]       2 MB

// ---------- packed f32x2 helpers (sm_103a) ----------
__device__ __forceinline__ unsigned long long ffma2(unsigned long long a,
                                                    unsigned long long b,
                                                    unsigned long long c) {
    unsigned long long d;
    asm("fma.rn.f32x2 %0, %1, %2, %3;" : "=l"(d) : "l"(a), "l"(b), "l"(c));
    return d;
}
__device__ __forceinline__ float2 unpk(unsigned long long v) {
    float2 f;
    asm("mov.b64 {%0, %1}, %2;" : "=f"(f.x), "=f"(f.y) : "l"(v));
    return f;
}

// ============================================================================
// Kernel 1: T2[b][q][c] = sum_d targetT[b][q][d] * W[d][c]
//   targetT[b][q][d] = input[b][d>>8][q][d&255]
//   Grid: (16 ksplit, 64 b). Block 128 thr. Tile: M=32(q) x N=256(c), K=512.
//   Per-thread 8m x 8n. A duplicated into pairs (STS.128), m-group is
//   warp-uniform so A LDS.128 is pure broadcast.
// ============================================================================
#define RSA 68   // As2 row stride: 64 floats (pairs for 32 m) + pad

__global__ __launch_bounds__(128) void k1_gemm_T2(const float* __restrict__ inp,
                                                  const float* __restrict__ W) {
    __shared__ float As2[32 * RSA];    // [kk][2m] duplicated A   (8.7 KB)
    __shared__ float Bs[32 * 256];     // [kk][n]                 (32 KB)
    const int b   = blockIdx.y;
    const int ks  = blockIdx.x;
    const int tid = threadIdx.x;
    const int mg  = tid >> 5;   // 0..3  (warp-uniform) -> m rows 8mg..8mg+7
    const int ng  = tid & 31;   // 0..31 -> n cols 8ng..8ng+7

    unsigned long long acc[8][4];
#pragma unroll
    for (int i = 0; i < 8; ++i)
#pragma unroll
        for (int j = 0; j < 4; ++j) acc[i][j] = 0ULL;

    const int mp = tid >> 3;    // 0..15 -> m pair (2mp, 2mp+1)
    const int kc = tid & 7;     // 0..7  -> k chunk 4kc..4kc+3

    const int kbeg = ks * (IDF_SZ / KSPLIT);
    const int kend = kbeg + (IDF_SZ / KSPLIT);
    for (int k0 = kbeg; k0 < kend; k0 += 32) {
        const int cl  = k0 >> 8;
        const int hw0 = k0 & 255;
        // ---- stage A: 32 m x 32 k, duplicated pairs, STS.128 ----
        {
            const float* ap = inp + ((b * 32 + cl) * 32 + 2 * mp) * 256 + hw0 + 4 * kc;
            float4 a0 = *(const float4*)(ap);
            float4 a1 = *(const float4*)(ap + 256);
            float* d0 = As2 + (4 * kc) * RSA + 4 * mp;
            *(float4*)(d0)           = make_float4(a0.x, a0.x, a1.x, a1.x);
            *(float4*)(d0 + RSA)     = make_float4(a0.y, a0.y, a1.y, a1.y);
            *(float4*)(d0 + 2 * RSA) = make_float4(a0.z, a0.z, a1.z, a1.z);
            *(float4*)(d0 + 3 * RSA) = make_float4(a0.w, a0.w, a1.w, a1.w);
        }
        // ---- stage B: 32 k x 256 n (coalesced) ----
#pragma unroll
        for (int i = 0; i < 16; ++i) {
            int idx = tid + i * 128;           // 0..2047 float4s
            int kk = idx >> 6, v = idx & 63;
            *(float4*)(Bs + kk * 256 + 4 * v) =
                *(const float4*)(W + (k0 + kk) * 256 + 4 * v);
        }
        __syncthreads();
#pragma unroll
        for (int kk = 0; kk < 32; ++kk) {
            const float* ar = As2 + kk * RSA + 16 * mg;
            ulonglong2 a01 = *(const ulonglong2*)(ar);
            ulonglong2 a23 = *(const ulonglong2*)(ar + 4);
            ulonglong2 a45 = *(const ulonglong2*)(ar + 8);
            ulonglong2 a67 = *(const ulonglong2*)(ar + 12);
            const float* br = Bs + kk * 256 + 8 * ng;
            ulonglong2 b01 = *(const ulonglong2*)(br);
            ulonglong2 b23 = *(const ulonglong2*)(br + 4);
            unsigned long long av[8] = {a01.x, a01.y, a23.x, a23.y,
                                        a45.x, a45.y, a67.x, a67.y};
            unsigned long long bv[4] = {b01.x, b01.y, b23.x, b23.y};
#pragma unroll
            for (int i = 0; i < 8; ++i)
#pragma unroll
                for (int j = 0; j < 4; ++j)
                    acc[i][j] = ffma2(av[i], bv[j], acc[i][j]);
        }
        __syncthreads();
    }
    float* dst = g_T2p + (size_t)ks * T2_STRIDE + b * 8192;
#pragma unroll
    for (int i = 0; i < 8; ++i) {
        int m = 8 * mg + i;
        float2 p0 = unpk(acc[i][0]), p1 = unpk(acc[i][1]);
        float2 p2 = unpk(acc[i][2]), p3 = unpk(acc[i][3]);
        *(float4*)(dst + m * 256 + 8 * ng)     = make_float4(p0.x, p0.y, p1.x, p1.y);
        *(float4*)(dst + m * 256 + 8 * ng + 4) = make_float4(p2.x, p2.y, p3.x, p3.y);
    }
}

// ============================================================================
// Kernel 2 (4 blocks per b, each handles 8 q-rows; 256 threads):
//   reduce T2 partials, logits, softmax, write attnT[b][s][q], ctx_attn.
// ============================================================================
#define APAD 133

__global__ __launch_bounds__(256) void k2_attn(const float* __restrict__ ctx,
                                               float* __restrict__ outAttnT) {
    __shared__ float T2s[8 * 256];     // [qlocal][c]
    __shared__ float attn[8 * APAD];   // [qlocal][s]

    const int b   = blockIdx.x >> 2;
    const int q0  = (blockIdx.x & 3) * 8;
    const int tid = threadIdx.x;

    // reduce 16 k-split partials for our 8 q rows (2048 floats = 512 float4)
#pragma unroll
    for (int i = 0; i < 2; ++i) {
        int idx = tid + i * 256;               // 0..511
        int ql  = idx >> 6;                    // 64 float4 per q row
        int cc  = (idx & 63) * 4;
        const float* src = g_T2p + (b * 32 + q0 + ql) * 256 + cc;
        float4 s = *(const float4*)(src);
#pragma unroll
        for (int p = 1; p < KSPLIT; ++p) {
            float4 t = *(const float4*)(src + (size_t)p * T2_STRIDE);
            s.x += t.x; s.y += t.y; s.z += t.z; s.w += t.w;
        }
        *(float4*)(T2s + 4 * idx) = s;
    }
    __syncthreads();

    // logits: attn[ql][s] = sum_c T2s[ql][c] * ctx[b][c][s]
    {
        const int s = tid & 127;
        const int g = tid >> 7;        // 0/1 -> ql 4g..4g+3
        float acc[4] = {0.f, 0.f, 0.f, 0.f};
        const float* cb = ctx + b * 256 * 128 + s;
        const float* t2 = T2s + g * 4 * 256;
        for (int c = 0; c < 256; ++c) {
            float cv = cb[c * 128];
#pragma unroll
            for (int j = 0; j < 4; ++j)
                acc[j] += t2[j * 256 + c] * cv;
        }
#pragma unroll
        for (int j = 0; j < 4; ++j) attn[(g * 4 + j) * APAD + s] = acc[j];
    }
    __syncthreads();

    // softmax over s (128) per row; 8 warps, one row each
    {
        const int warp = tid >> 5, lane = tid & 31;
        float v0 = attn[warp * APAD + lane];
        float v1 = attn[warp * APAD + lane + 32];
        float v2 = attn[warp * APAD + lane + 64];
        float v3 = attn[warp * APAD + lane + 96];
        float mx = fmaxf(fmaxf(v0, v1), fmaxf(v2, v3));
#pragma unroll
        for (int o = 16; o > 0; o >>= 1)
            mx = fmaxf(mx, __shfl_xor_sync(0xffffffffu, mx, o));
        float e0 = expf(v0 - mx), e1 = expf(v1 - mx);
        float e2 = expf(v2 - mx), e3 = expf(v3 - mx);
        float sm = e0 + e1 + e2 + e3;
#pragma unroll
        for (int o = 16; o > 0; o >>= 1)
            sm += __shfl_xor_sync(0xffffffffu, sm, o);
        float inv = 1.0f / sm;
        attn[warp * APAD + lane]      = e0 * inv;
        attn[warp * APAD + lane + 32] = e1 * inv;
        attn[warp * APAD + lane + 64] = e2 * inv;
        attn[warp * APAD + lane + 96] = e3 * inv;
    }
    __syncthreads();

    // attnT output: [b][s][q0+ql]
#pragma unroll
    for (int i = 0; i < 4; ++i) {
        int idx = tid + i * 256;           // 0..1023
        int s = idx >> 3, ql = idx & 7;
        outAttnT[b * 4096 + s * 32 + q0 + ql] = attn[ql * APAD + s];
    }

    // ctx_attn[b][c][q0..q0+7] = sum_s ctx[b][c][s] * attn[ql][s]
    {
        const int c = tid;                 // 0..255
        float a2[8] = {0.f,0.f,0.f,0.f,0.f,0.f,0.f,0.f};
        const float* cb = ctx + (b * 256 + c) * 128;
        for (int s = 0; s < 128; ++s) {
            float cv = cb[s];
#pragma unroll
            for (int j = 0; j < 8; ++j)
                a2[j] += attn[j * APAD + s] * cv;
        }
        float* dst = g_CA + (b * 256 + c) * 32 + q0;
        *(float4*)(dst)     = make_float4(a2[0], a2[1], a2[2], a2[3]);
        *(float4*)(dst + 4) = make_float4(a2[4], a2[5], a2[6], a2[7]);
    }
}

// ============================================================================
// Kernel 3: wc[b][d][q] = sum_c W[d][c] * ctx_attn[b][c][q], torch-.view write
//   out[b][c2][q2][hw]: c2=(d>>3)&31, q2=d>>8, hw=(d&7)*32+q
//   Grid: (32 m-tiles, 64 b). Block 128. Tile M=256(d) x N=32(q), K=256.
//   Per-thread 8m x 8q, W duplicated into pairs (STS.128), 8-kk chunks.
// ============================================================================
#define RSW 516   // Ws2 row stride: 512 floats (pairs for 256 m) + pad
#define KC3 8

__global__ __launch_bounds__(128) void k3_gemm_out(const float* __restrict__ W,
                                                   float* __restrict__ out0) {
    extern __shared__ float s3[];
    float* Cs  = s3;            // 256*32 floats [c][q]          (32 KB)
    float* Ws2 = s3 + 8192;     // KC3*RSW floats [kk][2m] dup   (16.5 KB)

    const int b   = blockIdx.y;
    const int m0  = blockIdx.x * 256;
    const int tid = threadIdx.x;
    const int mg  = tid >> 2;        // 0..31 -> m rows 8mg..8mg+7
    const int q0  = (tid & 3) * 8;   // 0,8,16,24

#pragma unroll
    for (int i = 0; i < 16; ++i) {
        int idx = tid + i * 128;     // 0..2047 float4s
        *(float4*)(Cs + 4 * idx) = *(const float4*)(g_CA + b * 8192 + 4 * idx);
    }

    unsigned long long acc[8][4];
#pragma unroll
    for (int i = 0; i < 8; ++i)
#pragma unroll
        for (int j = 0; j < 4; ++j) acc[i][j] = 0ULL;

    for (int k0 = 0; k0 < 256; k0 += KC3) {
        __syncthreads();   // first iter: Cs visible; later: Ws2 readers done
        // ---- stage W: 256 m x 8 k, duplicated pairs, STS.128 ----
        {
            const float* wp = W + (m0 + 2 * tid) * 256 + k0;
            float4 w00 = *(const float4*)(wp);
            float4 w01 = *(const float4*)(wp + 4);
            float4 w10 = *(const float4*)(wp + 256);
            float4 w11 = *(const float4*)(wp + 260);
            float* d0 = Ws2 + 4 * tid;
            *(float4*)(d0)           = make_float4(w00.x, w00.x, w10.x, w10.x);
            *(float4*)(d0 + RSW)     = make_float4(w00.y, w00.y, w10.y, w10.y);
            *(float4*)(d0 + 2 * RSW) = make_float4(w00.z, w00.z, w10.z, w10.z);
            *(float4*)(d0 + 3 * RSW) = make_float4(w00.w, w00.w, w10.w, w10.w);
            *(float4*)(d0 + 4 * RSW) = make_float4(w01.x, w01.x, w11.x, w11.x);
            *(float4*)(d0 + 5 * RSW) = make_float4(w01.y, w01.y, w11.y, w11.y);
            *(float4*)(d0 + 6 * RSW) = make_float4(w01.z, w01.z, w11.z, w11.z);
            *(float4*)(d0 + 7 * RSW) = make_float4(w01.w, w01.w, w11.w, w11.w);
        }
        __syncthreads();
#pragma unroll
        for (int kk = 0; kk < KC3; ++kk) {
            int c = k0 + kk;
            const float* ar = Ws2 + kk * RSW + 16 * mg;
            ulonglong2 a01 = *(const ulonglong2*)(ar);
            ulonglong2 a23 = *(const ulonglong2*)(ar + 4);
            ulonglong2 a45 = *(const ulonglong2*)(ar + 8);
            ulonglong2 a67 = *(const ulonglong2*)(ar + 12);
            const float* cr = Cs + c * 32 + q0;
            ulonglong2 c01 = *(const ulonglong2*)(cr);
            ulonglong2 c23 = *(const ulonglong2*)(cr + 4);
            unsigned long long av[8] = {a01.x, a01.y, a23.x, a23.y,
                                        a45.x, a45.y, a67.x, a67.y};
            unsigned long long cv[4] = {c01.x, c01.y, c23.x, c23.y};
#pragma unroll
            for (int i = 0; i < 8; ++i)
#pragma unroll
                for (int j = 0; j < 4; ++j)
                    acc[i][j] = ffma2(av[i], cv[j], acc[i][j]);
        }
    }

#pragma unroll
    for (int i = 0; i < 8; ++i) {
        int d  = m0 + 8 * mg + i;
        int c2 = (d >> 3) & 31;
        int q2 = d >> 8;
        int base = ((b * 32 + c2) * 32 + q2) * 256 + (d & 7) * 32 + q0;
        float2 p0 = unpk(acc[i][0]), p1 = unpk(acc[i][1]);
        float2 p2 = unpk(acc[i][2]), p3 = unpk(acc[i][3]);
        *(float4*)(out0 + base)     = make_float4(p0.x, p0.y, p1.x, p1.y);
        *(float4*)(out0 + base + 4) = make_float4(p2.x, p2.y, p3.x, p3.y);
    }
}

// ============================================================================
extern "C" void kernel_launch(void* const* d_in, const int* in_sizes, int n_in,
                              void* d_out, int out_size) {
    const float* inp = (const float*)d_in[0];   // input
    const float* ctx = (const float*)d_in[1];   // context
    const float* W   = (const float*)d_in[2];   // W [8192,256]
    float* out = (float*)d_out;

    const int SMEM3 = (8192 + KC3 * RSW) * 4;   // 49,280 B
    cudaFuncSetAttribute(k3_gemm_out, cudaFuncAttributeMaxDynamicSharedMemorySize, SMEM3);

    k1_gemm_T2<<<dim3(KSPLIT, B_SZ), 128>>>(inp, W);
    k2_attn<<<B_SZ * 4, 256>>>(ctx, out + WC_ELEMS);
    k3_gemm_out<<<dim3(32, B_SZ), 128, SMEM3>>>(W, out);
}

// round 5
// speedup vs baseline: 1.2726x; 1.2726x over previous
#include <cuda_runtime.h>

// Problem:
//   input   [64, 32, 32, 16, 16] f32   (B, CLN, QL, IH, IW)
//   context [64, 256, 128]       f32   (B, CDF, SL)
//   W       [8192, 256]          f32   (IDF, CDF)
// Outputs (concatenated in d_out):
//   wc    [64, 32, 32, 16, 16] f32  -> 16,777,216 elems
//   attnT [64, 128, 32]        f32  ->    262,144 elems
//
// tf32 2-split (h+l), 3 MMA passes (hh, hl, lh) per GEMM via
// mma.sync.aligned.m16n8k8.row.col.f32.tf32.tf32.f32  (baseline PTX, no 'a').

#define B_SZ   64
#define QL_SZ  32
#define CDF_SZ 256
#define SL_SZ  128
#define IDF_SZ 8192
#define WC_ELEMS (B_SZ * IDF_SZ * QL_SZ)   // 16777216
#define A_ELEMS  (B_SZ * QL_SZ * IDF_SZ)   // 16777216
#define W_ELEMS  (IDF_SZ * CDF_SZ)         // 2097152
#define KS1    8
#define MROWS  (B_SZ * QL_SZ)              // 2048
#define T2_STRIDE (MROWS * CDF_SZ)         // 524288

// ---------------- device scratch (tf32 stored as float) ----------------
__device__ __align__(16) float g_Ah[A_ELEMS];   // [b*32+q][8192]
__device__ __align__(16) float g_Al[A_ELEMS];
__device__ __align__(16) float g_Wh[W_ELEMS];   // [d][c]
__device__ __align__(16) float g_Wl[W_ELEMS];
__device__ __align__(16) float g_WTh[W_ELEMS];  // [c][d]
__device__ __align__(16) float g_WTl[W_ELEMS];
__device__ float g_T2p[KS1 * T2_STRIDE];        // 16 MB
__device__ __align__(16) float g_CAh[MROWS * CDF_SZ];  // [b*32+q][c]
__device__ __align__(16) float g_CAl[MROWS * CDF_SZ];

// ---------------- helpers ----------------
__device__ __forceinline__ float tf32r(float x) {
    unsigned u;
    asm("cvt.rna.tf32.f32 %0, %1;" : "=r"(u) : "f"(x));
    return __uint_as_float(u);
}
__device__ __forceinline__ void split2(float x, float& h, float& l) {
    h = tf32r(x);
    l = tf32r(x - h);
}
__device__ __forceinline__ void mma_tf32(float* c, float a0, float a1,
                                         float a2, float a3,
                                         float b0, float b1) {
    asm volatile(
        "mma.sync.aligned.m16n8k8.row.col.f32.tf32.tf32.f32 "
        "{%0,%1,%2,%3}, {%4,%5,%6,%7}, {%8,%9}, {%0,%1,%2,%3};"
        : "+f"(c[0]), "+f"(c[1]), "+f"(c[2]), "+f"(c[3])
        : "r"(__float_as_uint(a0)), "r"(__float_as_uint(a1)),
          "r"(__float_as_uint(a2)), "r"(__float_as_uint(a3)),
          "r"(__float_as_uint(b0)), "r"(__float_as_uint(b1)));
}

// ============================================================================
// k0a: gather+split input -> g_Ah/g_Al in [b*32+q][d] layout (d = cl*256+hw)
// ============================================================================
__global__ __launch_bounds__(256) void k0a_split_input(const float* __restrict__ inp) {
    int i4  = blockIdx.x * 256 + threadIdx.x;   // float4 index, 0..4194303
    int hw4 = i4 & 63;
    int q   = (i4 >> 6) & 31;
    int cl  = (i4 >> 11) & 31;
    int b   = i4 >> 16;
    float4 v = ((const float4*)inp)[i4];
    float4 h, l;
    split2(v.x, h.x, l.x); split2(v.y, h.y, l.y);
    split2(v.z, h.z, l.z); split2(v.w, h.w, l.w);
    int o = (b * 32 + q) * 8192 + cl * 256 + hw4 * 4;
    *(float4*)(g_Ah + o) = h;
    *(float4*)(g_Al + o) = l;
}

// ============================================================================
// k0b: split W native [d][c] and transposed [c][d]. Block = 32 d-rows.
// ============================================================================
__global__ __launch_bounds__(256) void k0b_split_W(const float* __restrict__ W) {
    __shared__ float tw[32 * 260];
    const int d0  = blockIdx.x * 32;
    const int tid = threadIdx.x;
    {
        int row = tid >> 3;
        int c0  = (tid & 7) * 32;
#pragma unroll
        for (int j = 0; j < 8; ++j) {
            float4 v = *(const float4*)(W + (d0 + row) * 256 + c0 + 4 * j);
            float4 h, l;
            split2(v.x, h.x, l.x); split2(v.y, h.y, l.y);
            split2(v.z, h.z, l.z); split2(v.w, h.w, l.w);
            int gi = (d0 + row) * 256 + c0 + 4 * j;
            *(float4*)(g_Wh + gi) = h;
            *(float4*)(g_Wl + gi) = l;
            *(float4*)(tw + row * 260 + c0 + 4 * j) = v;
        }
    }
    __syncthreads();
    {
        int c = tid;
#pragma unroll
        for (int jb = 0; jb < 4; ++jb) {
            float h8[8], l8[8];
#pragma unroll
            for (int i = 0; i < 8; ++i)
                split2(tw[(jb * 8 + i) * 260 + c], h8[i], l8[i]);
            int gi = c * IDF_SZ + d0 + jb * 8;
            *(float4*)(g_WTh + gi)     = make_float4(h8[0], h8[1], h8[2], h8[3]);
            *(float4*)(g_WTh + gi + 4) = make_float4(h8[4], h8[5], h8[6], h8[7]);
            *(float4*)(g_WTl + gi)     = make_float4(l8[0], l8[1], l8[2], l8[3]);
            *(float4*)(g_WTl + gi + 4) = make_float4(l8[4], l8[5], l8[6], l8[7]);
        }
    }
}

// ============================================================================
// k1: T2 partials.  Block tile M=128 (b·q rows) x N=128 (c), K=1024 per block.
//   Grid (32 = 16 mtiles x 2 ntiles, 8 ksplit).  256 thr = 8 warps (2m x 4n).
//   Warp tile 64x32; sub-tiles m16n8k8; kc=16 chunk; 3 tf32 passes.
// ============================================================================
#define STR 20   // smem tile row stride (16 + 4 pad): conflict-free frags

__global__ __launch_bounds__(256) void k1_mma() {
    __shared__ float sAh[128 * STR], sAl[128 * STR];
    __shared__ float sBh[128 * STR], sBl[128 * STR];
    const int mt = blockIdx.x >> 1, nt = blockIdx.x & 1, ks = blockIdx.y;
    const int m0 = mt * 128, n0 = nt * 128, kg0 = ks * 1024;
    const int tid = threadIdx.x, wid = tid >> 5, lane = tid & 31;
    const int mw = wid & 1, nw = wid >> 1;
    const int lr = lane >> 2, lc = lane & 3;

    float acc[4][4][4];
#pragma unroll
    for (int i = 0; i < 4; ++i)
#pragma unroll
        for (int j = 0; j < 4; ++j)
#pragma unroll
            for (int e = 0; e < 4; ++e) acc[i][j][e] = 0.0f;

    const int sr = tid >> 2, sc4 = (tid & 3) * 4;
    for (int ch = 0; ch < 64; ++ch) {
        const int kg = kg0 + ch * 16;
#pragma unroll
        for (int i = 0; i < 2; ++i) {
            int rr = sr + i * 64;
            *(float4*)(sAh + rr * STR + sc4) =
                *(const float4*)(g_Ah + (m0 + rr) * 8192 + kg + sc4);
            *(float4*)(sAl + rr * STR + sc4) =
                *(const float4*)(g_Al + (m0 + rr) * 8192 + kg + sc4);
            *(float4*)(sBh + rr * STR + sc4) =
                *(const float4*)(g_WTh + (n0 + rr) * 8192 + kg + sc4);
            *(float4*)(sBl + rr * STR + sc4) =
                *(const float4*)(g_WTl + (n0 + rr) * 8192 + kg + sc4);
        }
        __syncthreads();
#pragma unroll
        for (int p = 0; p < 3; ++p) {
            const float* sa = (p == 2) ? sAl : sAh;
            const float* sb = (p == 1) ? sBl : sBh;
#pragma unroll
            for (int k2 = 0; k2 < 2; ++k2) {
                const int kk = k2 * 8;
                float af[4][4];
#pragma unroll
                for (int sm = 0; sm < 4; ++sm) {
                    int rb = mw * 64 + sm * 16 + lr;
                    af[sm][0] = sa[rb * STR + kk + lc];
                    af[sm][1] = sa[(rb + 8) * STR + kk + lc];
                    af[sm][2] = sa[rb * STR + kk + lc + 4];
                    af[sm][3] = sa[(rb + 8) * STR + kk + lc + 4];
                }
                float bf[4][2];
#pragma unroll
                for (int sn = 0; sn < 4; ++sn) {
                    int nb = nw * 32 + sn * 8 + lr;
                    bf[sn][0] = sb[nb * STR + kk + lc];
                    bf[sn][1] = sb[nb * STR + kk + lc + 4];
                }
#pragma unroll
                for (int sm = 0; sm < 4; ++sm)
#pragma unroll
                    for (int sn = 0; sn < 4; ++sn)
                        mma_tf32(acc[sm][sn], af[sm][0], af[sm][1], af[sm][2],
                                 af[sm][3], bf[sn][0], bf[sn][1]);
            }
        }
        __syncthreads();
    }
    float* dst = g_T2p + (size_t)ks * T2_STRIDE;
#pragma unroll
    for (int sm = 0; sm < 4; ++sm) {
        int r = m0 + mw * 64 + sm * 16 + lr;
#pragma unroll
        for (int sn = 0; sn < 4; ++sn) {
            int c = n0 + nw * 32 + sn * 8 + 2 * lc;
            *(float2*)(dst + r * 256 + c) = make_float2(acc[sm][sn][0], acc[sm][sn][1]);
            *(float2*)(dst + (r + 8) * 256 + c) = make_float2(acc[sm][sn][2], acc[sm][sn][3]);
        }
    }
}

// ============================================================================
// k2 (4 blocks per b, 8 q-rows each, 256 threads):
//   reduce T2 partials, logits, softmax, attnT, CA -> tf32 split [b*32+q][c]
// ============================================================================
#define APAD 133

__global__ __launch_bounds__(256) void k2_attn(const float* __restrict__ ctx,
                                               float* __restrict__ outAttnT) {
    __shared__ float T2s[8 * 256];
    __shared__ float attn[8 * APAD];

    const int b   = blockIdx.x >> 2;
    const int q0  = (blockIdx.x & 3) * 8;
    const int tid = threadIdx.x;

#pragma unroll
    for (int i = 0; i < 2; ++i) {
        int idx = tid + i * 256;
        int ql  = idx >> 6;
        int cc  = (idx & 63) * 4;
        const float* src = g_T2p + (b * 32 + q0 + ql) * 256 + cc;
        float4 s = *(const float4*)(src);
#pragma unroll
        for (int p = 1; p < KS1; ++p) {
            float4 t = *(const float4*)(src + (size_t)p * T2_STRIDE);
            s.x += t.x; s.y += t.y; s.z += t.z; s.w += t.w;
        }
        *(float4*)(T2s + 4 * idx) = s;
    }
    __syncthreads();

    {
        const int s = tid & 127;
        const int g = tid >> 7;
        float acc[4] = {0.f, 0.f, 0.f, 0.f};
        const float* cb = ctx + b * 256 * 128 + s;
        const float* t2 = T2s + g * 4 * 256;
        for (int c = 0; c < 256; ++c) {
            float cv = cb[c * 128];
#pragma unroll
            for (int j = 0; j < 4; ++j)
                acc[j] += t2[j * 256 + c] * cv;
        }
#pragma unroll
        for (int j = 0; j < 4; ++j) attn[(g * 4 + j) * APAD + s] = acc[j];
    }
    __syncthreads();

    {
        const int warp = tid >> 5, lane = tid & 31;
        float v0 = attn[warp * APAD + lane];
        float v1 = attn[warp * APAD + lane + 32];
        float v2 = attn[warp * APAD + lane + 64];
        float v3 = attn[warp * APAD + lane + 96];
        float mx = fmaxf(fmaxf(v0, v1), fmaxf(v2, v3));
#pragma unroll
        for (int o = 16; o > 0; o >>= 1)
            mx = fmaxf(mx, __shfl_xor_sync(0xffffffffu, mx, o));
        float e0 = expf(v0 - mx), e1 = expf(v1 - mx);
        float e2 = expf(v2 - mx), e3 = expf(v3 - mx);
        float sm = e0 + e1 + e2 + e3;
#pragma unroll
        for (int o = 16; o > 0; o >>= 1)
            sm += __shfl_xor_sync(0xffffffffu, sm, o);
        float inv = 1.0f / sm;
        attn[warp * APAD + lane]      = e0 * inv;
        attn[warp * APAD + lane + 32] = e1 * inv;
        attn[warp * APAD + lane + 64] = e2 * inv;
        attn[warp * APAD + lane + 96] = e3 * inv;
    }
    __syncthreads();

#pragma unroll
    for (int i = 0; i < 4; ++i) {
        int idx = tid + i * 256;
        int s = idx >> 3, ql = idx & 7;
        outAttnT[b * 4096 + s * 32 + q0 + ql] = attn[ql * APAD + s];
    }

    {
        const int c = tid;
        float a2[8] = {0.f,0.f,0.f,0.f,0.f,0.f,0.f,0.f};
        const float* cb = ctx + (b * 256 + c) * 128;
        for (int s = 0; s < 128; ++s) {
            float cv = cb[s];
#pragma unroll
            for (int j = 0; j < 8; ++j)
                a2[j] += attn[j * APAD + s] * cv;
        }
#pragma unroll
        for (int j = 0; j < 8; ++j) {
            float h, l;
            split2(a2[j], h, l);
            int gi = (b * 32 + q0 + j) * 256 + c;
            g_CAh[gi] = h;
            g_CAl[gi] = l;
        }
    }
}

// ============================================================================
// k3: wc = W @ CA^T.  Block tile M=128 (d) x N=128 (4 b's x 32 q), K=256.
//   Grid (64 mtiles, 16 bgroups).  8 warps (4m x 2n), warp 32x64.
//   Epilogue applies the torch-.view scramble.
// ============================================================================
__global__ __launch_bounds__(256) void k3_mma(float* __restrict__ out0) {
    __shared__ float sAh[128 * STR], sAl[128 * STR];
    __shared__ float sBh[128 * STR], sBl[128 * STR];
    const int m0 = blockIdx.x * 128;
    const int b0 = blockIdx.y * 4;
    const int tid = threadIdx.x, wid = tid >> 5, lane = tid & 31;
    const int mw = wid & 3, nw = wid >> 2;
    const int lr = lane >> 2, lc = lane & 3;

    float acc[2][8][4];
#pragma unroll
    for (int i = 0; i < 2; ++i)
#pragma unroll
        for (int j = 0; j < 8; ++j)
#pragma unroll
            for (int e = 0; e < 4; ++e) acc[i][j][e] = 0.0f;

    const int sr = tid >> 2, sc4 = (tid & 3) * 4;
    for (int ch = 0; ch < 16; ++ch) {
        const int kg = ch * 16;
#pragma unroll
        for (int i = 0; i < 2; ++i) {
            int rr = sr + i * 64;
            *(float4*)(sAh + rr * STR + sc4) =
                *(const float4*)(g_Wh + (m0 + rr) * 256 + kg + sc4);
            *(float4*)(sAl + rr * STR + sc4) =
                *(const float4*)(g_Wl + (m0 + rr) * 256 + kg + sc4);
            *(float4*)(sBh + rr * STR + sc4) =
                *(const float4*)(g_CAh + (b0 * 32 + rr) * 256 + kg + sc4);
            *(float4*)(sBl + rr * STR + sc4) =
                *(const float4*)(g_CAl + (b0 * 32 + rr) * 256 + kg + sc4);
        }
        __syncthreads();
#pragma unroll
        for (int p = 0; p < 3; ++p) {
            const float* sa = (p == 2) ? sAl : sAh;
            const float* sb = (p == 1) ? sBl : sBh;
#pragma unroll
            for (int k2 = 0; k2 < 2; ++k2) {
                const int kk = k2 * 8;
                float af[2][4];
#pragma unroll
                for (int sm = 0; sm < 2; ++sm) {
                    int rb = mw * 32 + sm * 16 + lr;
                    af[sm][0] = sa[rb * STR + kk + lc];
                    af[sm][1] = sa[(rb + 8) * STR + kk + lc];
                    af[sm][2] = sa[rb * STR + kk + lc + 4];
                    af[sm][3] = sa[(rb + 8) * STR + kk + lc + 4];
                }
                float bf[8][2];
#pragma unroll
                for (int sn = 0; sn < 8; ++sn) {
                    int nb = nw * 64 + sn * 8 + lr;
                    bf[sn][0] = sb[nb * STR + kk + lc];
                    bf[sn][1] = sb[nb * STR + kk + lc + 4];
                }
#pragma unroll
                for (int sm = 0; sm < 2; ++sm)
#pragma unroll
                    for (int sn = 0; sn < 8; ++sn)
                        mma_tf32(acc[sm][sn], af[sm][0], af[sm][1], af[sm][2],
                                 af[sm][3], bf[sn][0], bf[sn][1]);
            }
        }
        __syncthreads();
    }

#pragma unroll
    for (int sm = 0; sm < 2; ++sm) {
        int dbase = m0 + mw * 32 + sm * 16 + lr;
#pragma unroll
        for (int sn = 0; sn < 8; ++sn) {
            int n = nw * 64 + sn * 8 + 2 * lc;
            int b = b0 + (n >> 5);
            int q = n & 31;
#pragma unroll
            for (int hf = 0; hf < 2; ++hf) {
                int d   = dbase + 8 * hf;
                int c2i = (d >> 3) & 31;
                int q2  = d >> 8;
                float* o = out0 + ((b * 32 + c2i) * 32 + q2) * 256 + (d & 7) * 32 + q;
                *(float2*)o = make_float2(acc[sm][sn][2 * hf], acc[sm][sn][2 * hf + 1]);
            }
        }
    }
}

// ============================================================================
extern "C" void kernel_launch(void* const* d_in, const int* in_sizes, int n_in,
                              void* d_out, int out_size) {
    const float* inp = (const float*)d_in[0];
    const float* ctx = (const float*)d_in[1];
    const float* W   = (const float*)d_in[2];
    float* out = (float*)d_out;

    k0a_split_input<<<A_ELEMS / 1024, 256>>>(inp);
    k0b_split_W<<<IDF_SZ / 32, 256>>>(W);
    k1_mma<<<dim3(32, KS1), 256>>>();
    k2_attn<<<B_SZ * 4, 256>>>(ctx, out + WC_ELEMS);
    k3_mma<<<dim3(64, 16), 256>>>(out);
}

// round 6
// speedup vs baseline: 1.5153x; 1.1907x over previous
#include <cuda_runtime.h>

// Problem:
//   input   [64, 32, 32, 16, 16] f32  -> A rows [b*32+q][d], d = cl*256+hw
//   context [64, 256, 128]       f32
//   W       [8192, 256]          f32
// Outputs: wc [64,32,32,16,16] f32 (16.7M) ; attnT [64,128,32] f32 (262K)
//
// tf32 2-split (h+l), 3 MMA passes (hh, hl, lh), m16n8k8.
// All GEMM operand arrays are stored with the k dimension PERMUTED in groups
// of 8: {k0,k4,k1,k5,k2,k6,k3,k7}, so MMA fragment pairs (k, k+4) are
// adjacent -> float2 LDS. cp.async double-buffered staging.

#define B_SZ   64
#define CDF_SZ 256
#define IDF_SZ 8192
#define WC_ELEMS (B_SZ * IDF_SZ * 32)      // 16777216
#define A_ELEMS  (B_SZ * 32 * IDF_SZ)
#define W_ELEMS  (IDF_SZ * CDF_SZ)
#define KS1    8
#define MROWS  (B_SZ * 32)                 // 2048
#define T2_STRIDE (MROWS * CDF_SZ)         // 524288

#define STRP   24                          // smem row stride (16 data + 8 pad)
#define ARRF   (128 * STRP)                // 3072 floats per array
#define STAGEF (4 * ARRF)                  // 12288 floats per stage
#define SMEM_GEMM (2 * STAGEF * 4)         // 98304 bytes

// ---------------- device scratch ----------------
__device__ __align__(16) float g_Ah[A_ELEMS];   // [row][dperm]
__device__ __align__(16) float g_Al[A_ELEMS];
__device__ __align__(16) float g_Wh[W_ELEMS];   // [d][cperm]
__device__ __align__(16) float g_Wl[W_ELEMS];
__device__ __align__(16) float g_WTh[W_ELEMS];  // [c][dperm]
__device__ __align__(16) float g_WTl[W_ELEMS];
__device__ float g_T2p[KS1 * T2_STRIDE];        // 16 MB
__device__ __align__(16) float g_CAh[MROWS * CDF_SZ];  // [row][cperm]
__device__ __align__(16) float g_CAl[MROWS * CDF_SZ];

// ---------------- helpers ----------------
__device__ __forceinline__ float tf32r(float x) {
    unsigned u;
    asm("cvt.rna.tf32.f32 %0, %1;" : "=r"(u) : "f"(x));
    return __uint_as_float(u);
}
__device__ __forceinline__ void split2(float x, float& h, float& l) {
    h = tf32r(x);
    l = tf32r(x - h);
}
__device__ __forceinline__ void mma_tf32(float* c, float a0, float a1,
                                         float a2, float a3,
                                         float b0, float b1) {
    asm volatile(
        "mma.sync.aligned.m16n8k8.row.col.f32.tf32.tf32.f32 "
        "{%0,%1,%2,%3}, {%4,%5,%6,%7}, {%8,%9}, {%0,%1,%2,%3};"
        : "+f"(c[0]), "+f"(c[1]), "+f"(c[2]), "+f"(c[3])
        : "r"(__float_as_uint(a0)), "r"(__float_as_uint(a1)),
          "r"(__float_as_uint(a2)), "r"(__float_as_uint(a3)),
          "r"(__float_as_uint(b0)), "r"(__float_as_uint(b1)));
}
__device__ __forceinline__ unsigned smem_u32(const void* p) {
    unsigned a;
    asm("{ .reg .u64 t; cvta.to.shared.u64 t, %1; cvt.u32.u64 %0, t; }"
        : "=r"(a) : "l"(p));
    return a;
}
__device__ __forceinline__ void cpa16(unsigned dst, const float* src) {
    asm volatile("cp.async.cg.shared.global [%0], [%1], 16;"
                 :: "r"(dst), "l"(src));
}
#define CP_COMMIT() asm volatile("cp.async.commit_group;" ::: "memory")
#define CP_WAIT(N)  asm volatile("cp.async.wait_group %0;" :: "n"(N) : "memory")
__device__ __forceinline__ int permk(int k) {
    return (k & ~7) | ((k & 3) << 1) | ((k >> 2) & 1);
}
// store 8 values (v[0..7] = orig k..k+7) as two permuted float4s
__device__ __forceinline__ void store_perm8(float* dst, const float* v) {
    *(float4*)(dst)     = make_float4(v[0], v[4], v[1], v[5]);
    *(float4*)(dst + 4) = make_float4(v[2], v[6], v[3], v[7]);
}

// ============================================================================
// k0a: gather+split input -> g_Ah/g_Al [b*32+q][dperm]
// ============================================================================
__global__ __launch_bounds__(256) void k0a_split_input(const float* __restrict__ inp) {
    int i8  = blockIdx.x * 256 + threadIdx.x;   // 8-float group index
    int hw8 = (i8 & 31) * 8;
    int q   = (i8 >> 5) & 31;
    int cl  = (i8 >> 10) & 31;
    int b   = i8 >> 15;
    const float* src = inp + (((b * 32 + cl) * 32 + q) << 8) + hw8;
    float4 v0 = *(const float4*)(src);
    float4 v1 = *(const float4*)(src + 4);
    float x[8] = {v0.x, v0.y, v0.z, v0.w, v1.x, v1.y, v1.z, v1.w};
    float h[8], l[8];
#pragma unroll
    for (int e = 0; e < 8; ++e) split2(x[e], h[e], l[e]);
    int o = (b * 32 + q) * 8192 + cl * 256 + hw8;
    store_perm8(g_Ah + o, h);
    store_perm8(g_Al + o, l);
}

// ============================================================================
// k0b: split W -> native [d][cperm] and transposed [c][dperm]
// ============================================================================
__global__ __launch_bounds__(256) void k0b_split_W(const float* __restrict__ W) {
    __shared__ float tw[32 * 260];
    const int d0  = blockIdx.x * 32;
    const int tid = threadIdx.x;
    {
        int row = tid >> 3;
        int c0  = (tid & 7) * 32;
#pragma unroll
        for (int grp = 0; grp < 4; ++grp) {
            int cb = c0 + grp * 8;
            float4 v0 = *(const float4*)(W + (d0 + row) * 256 + cb);
            float4 v1 = *(const float4*)(W + (d0 + row) * 256 + cb + 4);
            float x[8] = {v0.x, v0.y, v0.z, v0.w, v1.x, v1.y, v1.z, v1.w};
            float h[8], l[8];
#pragma unroll
            for (int e = 0; e < 8; ++e) split2(x[e], h[e], l[e]);
            store_perm8(g_Wh + (d0 + row) * 256 + cb, h);
            store_perm8(g_Wl + (d0 + row) * 256 + cb, l);
            *(float4*)(tw + row * 260 + cb)     = v0;
            *(float4*)(tw + row * 260 + cb + 4) = v1;
        }
    }
    __syncthreads();
    {
        int c = tid;
#pragma unroll
        for (int jb = 0; jb < 4; ++jb) {
            float h[8], l[8];
#pragma unroll
            for (int i = 0; i < 8; ++i)
                split2(tw[(jb * 8 + i) * 260 + c], h[i], l[i]);
            int gi = c * IDF_SZ + d0 + jb * 8;
            store_perm8(g_WTh + gi, h);
            store_perm8(g_WTl + gi, l);
        }
    }
}

// ============================================================================
// k1: T2 partials. M=128(row) x N=128(c), K=1024/block (64 chunks of 16).
//   Grid (32 = 16mt x 2nt, 8 ks). 8 warps (2m x 4n), warp 64x32.
//   cp.async double-buffered, float2 frag loads via pair-permuted layout.
// ============================================================================
__global__ __launch_bounds__(256, 2) void k1_mma() {
    extern __shared__ float smf[];
    const int mt = blockIdx.x >> 1, nt = blockIdx.x & 1, ks = blockIdx.y;
    const int m0 = mt * 128, n0 = nt * 128, kg0 = ks * 1024;
    const int tid = threadIdx.x, wid = tid >> 5, lane = tid & 31;
    const int mw = wid & 1, nw = wid >> 1;
    const int lr = lane >> 2, lc = lane & 3;
    const unsigned smb = smem_u32(smf);

    const int ldr = (tid & 511) >> 2;      // not used directly; see loop
    (void)ldr;

    float acc[4][4][4];
#pragma unroll
    for (int i = 0; i < 4; ++i)
#pragma unroll
        for (int j = 0; j < 4; ++j)
#pragma unroll
            for (int e = 0; e < 4; ++e) acc[i][j][e] = 0.0f;

    // stage loader: arrays {Ah, Al, WTh, WTl}; 16 floats/row
    auto load_stage = [&](int st, int ch) {
        const int kg = kg0 + ch * 16;
        const unsigned sb = smb + (st * STAGEF) * 4;
#pragma unroll
        for (int it = 0; it < 8; ++it) {
            int arr = it >> 1;
            int rem = (it & 1) * 256 + tid;    // 0..511
            int r = rem >> 2, seg = rem & 3;
            unsigned dst = sb + (arr * ARRF + r * STRP + seg * 4) * 4;
            const float* src;
            if (arr == 0)      src = g_Ah  + (size_t)(m0 + r) * 8192 + kg + seg * 4;
            else if (arr == 1) src = g_Al  + (size_t)(m0 + r) * 8192 + kg + seg * 4;
            else if (arr == 2) src = g_WTh + (size_t)(n0 + r) * 8192 + kg + seg * 4;
            else               src = g_WTl + (size_t)(n0 + r) * 8192 + kg + seg * 4;
            cpa16(dst, src);
        }
    };

    load_stage(0, 0);
    CP_COMMIT();

    for (int ch = 0; ch < 64; ++ch) {
        const int st = ch & 1;
        if (ch + 1 < 64) {
            load_stage(st ^ 1, ch + 1);
            CP_COMMIT();
            CP_WAIT(1);
        } else {
            CP_WAIT(0);
        }
        __syncthreads();
        const float* base = smf + st * STAGEF;
#pragma unroll
        for (int p = 0; p < 3; ++p) {
            const float* sa = base + ((p == 2) ? ARRF : 0);
            const float* sb = base + ((p == 1) ? 3 * ARRF : 2 * ARRF);
#pragma unroll
            for (int k2 = 0; k2 < 2; ++k2) {
                const int ko = k2 * 8 + lc * 2;
                float2 a0[4], a1[4];
#pragma unroll
                for (int sm = 0; sm < 4; ++sm) {
                    int rb = mw * 64 + sm * 16 + lr;
                    a0[sm] = *(const float2*)(sa + rb * STRP + ko);
                    a1[sm] = *(const float2*)(sa + (rb + 8) * STRP + ko);
                }
                float2 bf[4];
#pragma unroll
                for (int sn = 0; sn < 4; ++sn) {
                    int nb = nw * 32 + sn * 8 + lr;
                    bf[sn] = *(const float2*)(sb + nb * STRP + ko);
                }
#pragma unroll
                for (int sm = 0; sm < 4; ++sm)
#pragma unroll
                    for (int sn = 0; sn < 4; ++sn)
                        mma_tf32(acc[sm][sn], a0[sm].x, a1[sm].x,
                                 a0[sm].y, a1[sm].y, bf[sn].x, bf[sn].y);
            }
        }
        __syncthreads();
    }

    float* dst = g_T2p + (size_t)ks * T2_STRIDE;
#pragma unroll
    for (int sm = 0; sm < 4; ++sm) {
        int r = m0 + mw * 64 + sm * 16 + lr;
#pragma unroll
        for (int sn = 0; sn < 4; ++sn) {
            int c = n0 + nw * 32 + sn * 8 + 2 * lc;
            *(float2*)(dst + r * 256 + c) = make_float2(acc[sm][sn][0], acc[sm][sn][1]);
            *(float2*)(dst + (r + 8) * 256 + c) = make_float2(acc[sm][sn][2], acc[sm][sn][3]);
        }
    }
}

// ============================================================================
// k2 (8 blocks per b, 4 q-rows each, 256 threads)
// ============================================================================
#define APAD 133

__global__ __launch_bounds__(256) void k2_attn(const float* __restrict__ ctx,
                                               float* __restrict__ outAttnT) {
    __shared__ float T2s[4 * 256];
    __shared__ float attn[4 * APAD];

    const int b   = blockIdx.x >> 3;
    const int q0  = (blockIdx.x & 7) * 4;
    const int tid = threadIdx.x;

    // reduce 8 k-split partials: 4 rows x 256 c = 256 float4
    {
        int ql = tid >> 6;
        int cc = (tid & 63) * 4;
        const float* src = g_T2p + (b * 32 + q0 + ql) * 256 + cc;
        float4 s = *(const float4*)(src);
#pragma unroll
        for (int p = 1; p < KS1; ++p) {
            float4 t = *(const float4*)(src + (size_t)p * T2_STRIDE);
            s.x += t.x; s.y += t.y; s.z += t.z; s.w += t.w;
        }
        *(float4*)(T2s + ql * 256 + cc) = s;
    }
    __syncthreads();

    {
        const int s = tid & 127;
        const int g = tid >> 7;
        float a0 = 0.f, a1 = 0.f;
        const float* cb = ctx + b * 32768 + s;
        const float* t2 = T2s + g * 512;
        for (int c = 0; c < 256; ++c) {
            float cv = cb[c * 128];
            a0 += t2[c] * cv;
            a1 += t2[256 + c] * cv;
        }
        attn[(2 * g) * APAD + s]     = a0;
        attn[(2 * g + 1) * APAD + s] = a1;
    }
    __syncthreads();

    {
        const int warp = tid >> 5, lane = tid & 31;
        if (warp < 4) {
            float v0 = attn[warp * APAD + lane];
            float v1 = attn[warp * APAD + lane + 32];
            float v2 = attn[warp * APAD + lane + 64];
            float v3 = attn[warp * APAD + lane + 96];
            float mx = fmaxf(fmaxf(v0, v1), fmaxf(v2, v3));
#pragma unroll
            for (int o = 16; o > 0; o >>= 1)
                mx = fmaxf(mx, __shfl_xor_sync(0xffffffffu, mx, o));
            float e0 = expf(v0 - mx), e1 = expf(v1 - mx);
            float e2 = expf(v2 - mx), e3 = expf(v3 - mx);
            float sm = e0 + e1 + e2 + e3;
#pragma unroll
            for (int o = 16; o > 0; o >>= 1)
                sm += __shfl_xor_sync(0xffffffffu, sm, o);
            float inv = 1.0f / sm;
            attn[warp * APAD + lane]      = e0 * inv;
            attn[warp * APAD + lane + 32] = e1 * inv;
            attn[warp * APAD + lane + 64] = e2 * inv;
            attn[warp * APAD + lane + 96] = e3 * inv;
        }
    }
    __syncthreads();

#pragma unroll
    for (int i = 0; i < 2; ++i) {
        int idx = tid + i * 256;           // 0..511
        int s = idx >> 2, ql = idx & 3;
        outAttnT[b * 4096 + s * 32 + q0 + ql] = attn[ql * APAD + s];
    }

    {
        const int c = tid;                 // 0..255
        float a2[4] = {0.f, 0.f, 0.f, 0.f};
        const float* cb = ctx + (b * 256 + c) * 128;
        for (int s = 0; s < 128; ++s) {
            float cv = cb[s];
#pragma unroll
            for (int j = 0; j < 4; ++j)
                a2[j] += attn[j * APAD + s] * cv;
        }
        int cp = permk(c);
#pragma unroll
        for (int j = 0; j < 4; ++j) {
            float h, l;
            split2(a2[j], h, l);
            int gi = (b * 32 + q0 + j) * 256 + cp;
            g_CAh[gi] = h;
            g_CAl[gi] = l;
        }
    }
}

// ============================================================================
// k3: wc = W @ CA^T.  M=128(d) x N=128(4b x 32q), K=256 (16 chunks).
//   Grid (64 mt, 16 bg). Same cp.async machinery. .view-scramble epilogue.
// ============================================================================
__global__ __launch_bounds__(256, 2) void k3_mma(float* __restrict__ out0) {
    extern __shared__ float smf[];
    const int m0 = blockIdx.x * 128;
    const int b0 = blockIdx.y * 4;
    const int tid = threadIdx.x, wid = tid >> 5, lane = tid & 31;
    const int mw = wid & 3, nw = wid >> 2;
    const int lr = lane >> 2, lc = lane & 3;
    const unsigned smb = smem_u32(smf);

    float acc[2][8][4];
#pragma unroll
    for (int i = 0; i < 2; ++i)
#pragma unroll
        for (int j = 0; j < 8; ++j)
#pragma unroll
            for (int e = 0; e < 4; ++e) acc[i][j][e] = 0.0f;

    auto load_stage = [&](int st, int ch) {
        const int kg = ch * 16;
        const unsigned sb = smb + (st * STAGEF) * 4;
#pragma unroll
        for (int it = 0; it < 8; ++it) {
            int arr = it >> 1;
            int rem = (it & 1) * 256 + tid;
            int r = rem >> 2, seg = rem & 3;
            unsigned dst = sb + (arr * ARRF + r * STRP + seg * 4) * 4;
            const float* src;
            if (arr == 0)      src = g_Wh  + (size_t)(m0 + r) * 256 + kg + seg * 4;
            else if (arr == 1) src = g_Wl  + (size_t)(m0 + r) * 256 + kg + seg * 4;
            else if (arr == 2) src = g_CAh + (size_t)(b0 * 32 + r) * 256 + kg + seg * 4;
            else               src = g_CAl + (size_t)(b0 * 32 + r) * 256 + kg + seg * 4;
            cpa16(dst, src);
        }
    };

    load_stage(0, 0);
    CP_COMMIT();

    for (int ch = 0; ch < 16; ++ch) {
        const int st = ch & 1;
        if (ch + 1 < 16) {
            load_stage(st ^ 1, ch + 1);
            CP_COMMIT();
            CP_WAIT(1);
        } else {
            CP_WAIT(0);
        }
        __syncthreads();
        const float* base = smf + st * STAGEF;
#pragma unroll
        for (int p = 0; p < 3; ++p) {
            const float* sa = base + ((p == 2) ? ARRF : 0);
            const float* sb = base + ((p == 1) ? 3 * ARRF : 2 * ARRF);
#pragma unroll
            for (int k2 = 0; k2 < 2; ++k2) {
                const int ko = k2 * 8 + lc * 2;
                float2 a0[2], a1[2];
#pragma unroll
                for (int sm = 0; sm < 2; ++sm) {
                    int rb = mw * 32 + sm * 16 + lr;
                    a0[sm] = *(const float2*)(sa + rb * STRP + ko);
                    a1[sm] = *(const float2*)(sa + (rb + 8) * STRP + ko);
                }
                float2 bf[8];
#pragma unroll
                for (int sn = 0; sn < 8; ++sn) {
                    int nb = nw * 64 + sn * 8 + lr;
                    bf[sn] = *(const float2*)(sb + nb * STRP + ko);
                }
#pragma unroll
                for (int sm = 0; sm < 2; ++sm)
#pragma unroll
                    for (int sn = 0; sn < 8; ++sn)
                        mma_tf32(acc[sm][sn], a0[sm].x, a1[sm].x,
                                 a0[sm].y, a1[sm].y, bf[sn].x, bf[sn].y);
            }
        }
        __syncthreads();
    }

#pragma unroll
    for (int sm = 0; sm < 2; ++sm) {
        int dbase = m0 + mw * 32 + sm * 16 + lr;
#pragma unroll
        for (int sn = 0; sn < 8; ++sn) {
            int n = nw * 64 + sn * 8 + 2 * lc;
            int b = b0 + (n >> 5);
            int q = n & 31;
#pragma unroll
            for (int hf = 0; hf < 2; ++hf) {
                int d   = dbase + 8 * hf;
                int c2i = (d >> 3) & 31;
                int q2  = d >> 8;
                float* o = out0 + ((b * 32 + c2i) * 32 + q2) * 256 + (d & 7) * 32 + q;
                *(float2*)o = make_float2(acc[sm][sn][2 * hf], acc[sm][sn][2 * hf + 1]);
            }
        }
    }
}

// ============================================================================
extern "C" void kernel_launch(void* const* d_in, const int* in_sizes, int n_in,
                              void* d_out, int out_size) {
    const float* inp = (const float*)d_in[0];
    const float* ctx = (const float*)d_in[1];
    const float* W   = (const float*)d_in[2];
    float* out = (float*)d_out;

    static int inited = 0;
    if (!inited) {
        cudaFuncSetAttribute(k1_mma, cudaFuncAttributeMaxDynamicSharedMemorySize, SMEM_GEMM);
        cudaFuncSetAttribute(k3_mma, cudaFuncAttributeMaxDynamicSharedMemorySize, SMEM_GEMM);
        inited = 1;
    }

    k0a_split_input<<<A_ELEMS / 8 / 256, 256>>>(inp);
    k0b_split_W<<<IDF_SZ / 32, 256>>>(W);
    k1_mma<<<dim3(32, KS1), 256, SMEM_GEMM>>>();
    k2_attn<<<B_SZ * 8, 256>>>(ctx, out + WC_ELEMS);
    k3_mma<<<dim3(64, 16), 256, SMEM_GEMM>>>(out);
}

// round 7
// speedup vs baseline: 1.5888x; 1.0485x over previous
#include <cuda_runtime.h>

// Problem:
//   input   [64, 32, 32, 16, 16] f32  -> A rows [b*32+q][d], d = cl*256+hw
//   context [64, 256, 128]       f32
//   W       [8192, 256]          f32
// Outputs: wc [64,32,32,16,16] f32 (16.7M) ; attnT [64,128,32] f32 (262K)
//
// tf32 2-split (h+l), 3 MMA passes (hh, hl, lh), m16n8k8.
// k-dim pair-permuted {k0,k4,k1,k5,k2,k6,k3,k7} -> float2 frag LDS.
// k1 splits A in-kernel from raw input (no k0a pass). B via cp.async.

#define B_SZ   64
#define CDF_SZ 256
#define IDF_SZ 8192
#define WC_ELEMS (B_SZ * IDF_SZ * 32)      // 16777216
#define W_ELEMS  (IDF_SZ * CDF_SZ)
#define KS1    8
#define MROWS  (B_SZ * 32)                 // 2048
#define T2_STRIDE (MROWS * CDF_SZ)         // 524288

#define STRP   24                          // smem row stride (16 data + 8 pad)
#define ARRF   (128 * STRP)                // 3072 floats per array
#define STAGEF (4 * ARRF)                  // 12288 floats per stage
#define SMEM_GEMM (2 * STAGEF * 4)         // 98304 bytes

// ---------------- device scratch ----------------
__device__ __align__(16) float g_Wh[W_ELEMS];   // [d][cperm]
__device__ __align__(16) float g_Wl[W_ELEMS];
__device__ __align__(16) float g_WTh[W_ELEMS];  // [c][dperm]
__device__ __align__(16) float g_WTl[W_ELEMS];
__device__ float g_T2p[KS1 * T2_STRIDE];        // 16 MB
__device__ __align__(16) float g_CAh[MROWS * CDF_SZ];  // [row][cperm]
__device__ __align__(16) float g_CAl[MROWS * CDF_SZ];

// ---------------- helpers ----------------
__device__ __forceinline__ float tf32r(float x) {
    unsigned u;
    asm("cvt.rna.tf32.f32 %0, %1;" : "=r"(u) : "f"(x));
    return __uint_as_float(u);
}
__device__ __forceinline__ void split2(float x, float& h, float& l) {
    h = tf32r(x);
    l = tf32r(x - h);
}
__device__ __forceinline__ void mma_tf32(float* c, float a0, float a1,
                                         float a2, float a3,
                                         float b0, float b1) {
    asm volatile(
        "mma.sync.aligned.m16n8k8.row.col.f32.tf32.tf32.f32 "
        "{%0,%1,%2,%3}, {%4,%5,%6,%7}, {%8,%9}, {%0,%1,%2,%3};"
        : "+f"(c[0]), "+f"(c[1]), "+f"(c[2]), "+f"(c[3])
        : "r"(__float_as_uint(a0)), "r"(__float_as_uint(a1)),
          "r"(__float_as_uint(a2)), "r"(__float_as_uint(a3)),
          "r"(__float_as_uint(b0)), "r"(__float_as_uint(b1)));
}
__device__ __forceinline__ unsigned smem_u32(const void* p) {
    unsigned a;
    asm("{ .reg .u64 t; cvta.to.shared.u64 t, %1; cvt.u32.u64 %0, t; }"
        : "=r"(a) : "l"(p));
    return a;
}
__device__ __forceinline__ void cpa16(unsigned dst, const float* src) {
    asm volatile("cp.async.cg.shared.global [%0], [%1], 16;"
                 :: "r"(dst), "l"(src));
}
#define CP_COMMIT() asm volatile("cp.async.commit_group;" ::: "memory")
#define CP_WAIT(N)  asm volatile("cp.async.wait_group %0;" :: "n"(N) : "memory")
__device__ __forceinline__ int permk(int k) {
    return (k & ~7) | ((k & 3) << 1) | ((k >> 2) & 1);
}
// store 8 values (v[0..7] = orig k..k+7) as two permuted float4s
__device__ __forceinline__ void store_perm8(float* dst, const float* v) {
    *(float4*)(dst)     = make_float4(v[0], v[4], v[1], v[5]);
    *(float4*)(dst + 4) = make_float4(v[2], v[6], v[3], v[7]);
}

// ============================================================================
// k0b: split W -> native [d][cperm] and transposed [c][dperm]
// ============================================================================
__global__ __launch_bounds__(256) void k0b_split_W(const float* __restrict__ W) {
    __shared__ float tw[32 * 260];
    const int d0  = blockIdx.x * 32;
    const int tid = threadIdx.x;
    {
        int row = tid >> 3;
        int c0  = (tid & 7) * 32;
#pragma unroll
        for (int grp = 0; grp < 4; ++grp) {
            int cb = c0 + grp * 8;
            float4 v0 = *(const float4*)(W + (d0 + row) * 256 + cb);
            float4 v1 = *(const float4*)(W + (d0 + row) * 256 + cb + 4);
            float x[8] = {v0.x, v0.y, v0.z, v0.w, v1.x, v1.y, v1.z, v1.w};
            float h[8], l[8];
#pragma unroll
            for (int e = 0; e < 8; ++e) split2(x[e], h[e], l[e]);
            store_perm8(g_Wh + (d0 + row) * 256 + cb, h);
            store_perm8(g_Wl + (d0 + row) * 256 + cb, l);
            *(float4*)(tw + row * 260 + cb)     = v0;
            *(float4*)(tw + row * 260 + cb + 4) = v1;
        }
    }
    __syncthreads();
    {
        int c = tid;
#pragma unroll
        for (int jb = 0; jb < 4; ++jb) {
            float h[8], l[8];
#pragma unroll
            for (int i = 0; i < 8; ++i)
                split2(tw[(jb * 8 + i) * 260 + c], h[i], l[i]);
            int gi = c * IDF_SZ + d0 + jb * 8;
            store_perm8(g_WTh + gi, h);
            store_perm8(g_WTl + gi, l);
        }
    }
}

// ============================================================================
// k1: T2 partials. M=128(row) x N=128(c), K=1024/block (64 chunks of 16).
//   Grid (32 = 16mt x 2nt, 8 ks). 8 warps (2m x 4n), warp 64x32.
//   A: raw input LDG -> reg split -> STS (in-kernel tf32 split).
//   B: cp.async double-buffered pre-split WT.
// ============================================================================
__global__ __launch_bounds__(256, 2) void k1_mma(const float* __restrict__ inp) {
    extern __shared__ float smf[];
    const int mt = blockIdx.x >> 1, nt = blockIdx.x & 1, ks = blockIdx.y;
    const int m0 = mt * 128, n0 = nt * 128, kg0 = ks * 1024;
    const int tid = threadIdx.x, wid = tid >> 5, lane = tid & 31;
    const int mw = wid & 1, nw = wid >> 1;
    const int lr = lane >> 2, lc = lane & 3;
    const unsigned smb = smem_u32(smf);

    float acc[4][4][4];
#pragma unroll
    for (int i = 0; i < 4; ++i)
#pragma unroll
        for (int j = 0; j < 4; ++j)
#pragma unroll
            for (int e = 0; e < 4; ++e) acc[i][j][e] = 0.0f;

    // A loader geometry: thread owns row (tid>>1), 8 consecutive k at 8*(tid&1)
    const int arow = tid >> 1;           // 0..127
    const int ahalf = tid & 1;           // 0/1 -> k offset 0/8
    const int aR = m0 + arow;            // global row
    const int ab = aR >> 5, aq = aR & 31;
    // input addr for global k = kg: cl = kg>>8, hw = kg&255
    // addr = (((ab*32+cl)*32+aq)<<8) + hw + 8*ahalf

    // B loader: 2 arrays x 512 float4 / 256 thr = 4 cpa16
    auto load_B = [&](int st, int ch) {
        const int kg = kg0 + ch * 16;
        const unsigned sb = smb + (st * STAGEF) * 4;
#pragma unroll
        for (int it = 0; it < 4; ++it) {
            int arr = 2 + (it >> 1);
            int rem = (it & 1) * 256 + tid;
            int r = rem >> 2, seg = rem & 3;
            unsigned dst = sb + (arr * ARRF + r * STRP + seg * 4) * 4;
            const float* src = (arr == 2)
                ? g_WTh + (size_t)(n0 + r) * 8192 + kg + seg * 4
                : g_WTl + (size_t)(n0 + r) * 8192 + kg + seg * 4;
            cpa16(dst, src);
        }
    };
    auto load_A_regs = [&](int ch, float* xr) {
        const int kg = kg0 + ch * 16;
        const int cl = kg >> 8, hw = (kg & 255) + 8 * ahalf;
        const float* src = inp + (((ab * 32 + cl) * 32 + aq) << 8) + hw;
        float4 v0 = *(const float4*)(src);
        float4 v1 = *(const float4*)(src + 4);
        xr[0] = v0.x; xr[1] = v0.y; xr[2] = v0.z; xr[3] = v0.w;
        xr[4] = v1.x; xr[5] = v1.y; xr[6] = v1.z; xr[7] = v1.w;
    };

    float xr[8];
    load_A_regs(0, xr);
    load_B(0, 0);
    CP_COMMIT();

    for (int ch = 0; ch < 64; ++ch) {
        const int st = ch & 1;
        // split A(ch) regs -> smem stage st (stage last used by compute ch-2)
        {
            float h[8], l[8];
#pragma unroll
            for (int e = 0; e < 8; ++e) split2(xr[e], h[e], l[e]);
            float* base = smf + st * STAGEF + arow * STRP + 8 * ahalf;
            store_perm8(base, h);
            store_perm8(base + ARRF, l);
        }
        if (ch + 1 < 64) {
            load_A_regs(ch + 1, xr);
            load_B(st ^ 1, ch + 1);
            CP_COMMIT();
            CP_WAIT(1);
        } else {
            CP_WAIT(0);
        }
        __syncthreads();
        const float* base = smf + st * STAGEF;
#pragma unroll
        for (int p = 0; p < 3; ++p) {
            const float* sa = base + ((p == 2) ? ARRF : 0);
            const float* sb = base + ((p == 1) ? 3 * ARRF : 2 * ARRF);
#pragma unroll
            for (int k2 = 0; k2 < 2; ++k2) {
                const int ko = k2 * 8 + lc * 2;
                float2 a0[4], a1[4];
#pragma unroll
                for (int sm = 0; sm < 4; ++sm) {
                    int rb = mw * 64 + sm * 16 + lr;
                    a0[sm] = *(const float2*)(sa + rb * STRP + ko);
                    a1[sm] = *(const float2*)(sa + (rb + 8) * STRP + ko);
                }
                float2 bf[4];
#pragma unroll
                for (int sn = 0; sn < 4; ++sn) {
                    int nb = nw * 32 + sn * 8 + lr;
                    bf[sn] = *(const float2*)(sb + nb * STRP + ko);
                }
#pragma unroll
                for (int sm = 0; sm < 4; ++sm)
#pragma unroll
                    for (int sn = 0; sn < 4; ++sn)
                        mma_tf32(acc[sm][sn], a0[sm].x, a1[sm].x,
                                 a0[sm].y, a1[sm].y, bf[sn].x, bf[sn].y);
            }
        }
        __syncthreads();
    }

    float* dst = g_T2p + (size_t)ks * T2_STRIDE;
#pragma unroll
    for (int sm = 0; sm < 4; ++sm) {
        int r = m0 + mw * 64 + sm * 16 + lr;
#pragma unroll
        for (int sn = 0; sn < 4; ++sn) {
            int c = n0 + nw * 32 + sn * 8 + 2 * lc;
            *(float2*)(dst + r * 256 + c) = make_float2(acc[sm][sn][0], acc[sm][sn][1]);
            *(float2*)(dst + (r + 8) * 256 + c) = make_float2(acc[sm][sn][2], acc[sm][sn][3]);
        }
    }
}

// ============================================================================
// k2 (4 blocks per b, 8 q-rows each, 256 threads) — round-5 shape
// ============================================================================
#define APAD 133

__global__ __launch_bounds__(256) void k2_attn(const float* __restrict__ ctx,
                                               float* __restrict__ outAttnT) {
    __shared__ float T2s[8 * 256];
    __shared__ float attn[8 * APAD];

    const int b   = blockIdx.x >> 2;
    const int q0  = (blockIdx.x & 3) * 8;
    const int tid = threadIdx.x;

#pragma unroll
    for (int i = 0; i < 2; ++i) {
        int idx = tid + i * 256;
        int ql  = idx >> 6;
        int cc  = (idx & 63) * 4;
        const float* src = g_T2p + (b * 32 + q0 + ql) * 256 + cc;
        float4 s = *(const float4*)(src);
#pragma unroll
        for (int p = 1; p < KS1; ++p) {
            float4 t = *(const float4*)(src + (size_t)p * T2_STRIDE);
            s.x += t.x; s.y += t.y; s.z += t.z; s.w += t.w;
        }
        *(float4*)(T2s + 4 * idx) = s;
    }
    __syncthreads();

    {
        const int s = tid & 127;
        const int g = tid >> 7;
        float acc[4] = {0.f, 0.f, 0.f, 0.f};
        const float* cb = ctx + b * 32768 + s;
        const float* t2 = T2s + g * 4 * 256;
        for (int c = 0; c < 256; ++c) {
            float cv = cb[c * 128];
#pragma unroll
            for (int j = 0; j < 4; ++j)
                acc[j] += t2[j * 256 + c] * cv;
        }
#pragma unroll
        for (int j = 0; j < 4; ++j) attn[(g * 4 + j) * APAD + s] = acc[j];
    }
    __syncthreads();

    {
        const int warp = tid >> 5, lane = tid & 31;
        float v0 = attn[warp * APAD + lane];
        float v1 = attn[warp * APAD + lane + 32];
        float v2 = attn[warp * APAD + lane + 64];
        float v3 = attn[warp * APAD + lane + 96];
        float mx = fmaxf(fmaxf(v0, v1), fmaxf(v2, v3));
#pragma unroll
        for (int o = 16; o > 0; o >>= 1)
            mx = fmaxf(mx, __shfl_xor_sync(0xffffffffu, mx, o));
        float e0 = expf(v0 - mx), e1 = expf(v1 - mx);
        float e2 = expf(v2 - mx), e3 = expf(v3 - mx);
        float sm = e0 + e1 + e2 + e3;
#pragma unroll
        for (int o = 16; o > 0; o >>= 1)
            sm += __shfl_xor_sync(0xffffffffu, sm, o);
        float inv = 1.0f / sm;
        attn[warp * APAD + lane]      = e0 * inv;
        attn[warp * APAD + lane + 32] = e1 * inv;
        attn[warp * APAD + lane + 64] = e2 * inv;
        attn[warp * APAD + lane + 96] = e3 * inv;
    }
    __syncthreads();

#pragma unroll
    for (int i = 0; i < 4; ++i) {
        int idx = tid + i * 256;
        int s = idx >> 3, ql = idx & 7;
        outAttnT[b * 4096 + s * 32 + q0 + ql] = attn[ql * APAD + s];
    }

    {
        const int c = tid;
        float a2[8] = {0.f,0.f,0.f,0.f,0.f,0.f,0.f,0.f};
        const float* cb = ctx + (b * 256 + c) * 128;
        for (int s = 0; s < 128; ++s) {
            float cv = cb[s];
#pragma unroll
            for (int j = 0; j < 8; ++j)
                a2[j] += attn[j * APAD + s] * cv;
        }
        int cp = permk(c);
#pragma unroll
        for (int j = 0; j < 8; ++j) {
            float h, l;
            split2(a2[j], h, l);
            int gi = (b * 32 + q0 + j) * 256 + cp;
            g_CAh[gi] = h;
            g_CAl[gi] = l;
        }
    }
}

// ============================================================================
// k3: wc = W @ CA^T.  M=128(d) x N=128(4b x 32q), K=256 (16 chunks).
// ============================================================================
__global__ __launch_bounds__(256, 2) void k3_mma(float* __restrict__ out0) {
    extern __shared__ float smf[];
    const int m0 = blockIdx.x * 128;
    const int b0 = blockIdx.y * 4;
    const int tid = threadIdx.x, wid = tid >> 5, lane = tid & 31;
    const int mw = wid & 3, nw = wid >> 2;
    const int lr = lane >> 2, lc = lane & 3;
    const unsigned smb = smem_u32(smf);

    float acc[2][8][4];
#pragma unroll
    for (int i = 0; i < 2; ++i)
#pragma unroll
        for (int j = 0; j < 8; ++j)
#pragma unroll
            for (int e = 0; e < 4; ++e) acc[i][j][e] = 0.0f;

    auto load_stage = [&](int st, int ch) {
        const int kg = ch * 16;
        const unsigned sb = smb + (st * STAGEF) * 4;
#pragma unroll
        for (int it = 0; it < 8; ++it) {
            int arr = it >> 1;
            int rem = (it & 1) * 256 + tid;
            int r = rem >> 2, seg = rem & 3;
            unsigned dst = sb + (arr * ARRF + r * STRP + seg * 4) * 4;
            const float* src;
            if (arr == 0)      src = g_Wh  + (size_t)(m0 + r) * 256 + kg + seg * 4;
            else if (arr == 1) src = g_Wl  + (size_t)(m0 + r) * 256 + kg + seg * 4;
            else if (arr == 2) src = g_CAh + (size_t)(b0 * 32 + r) * 256 + kg + seg * 4;
            else               src = g_CAl + (size_t)(b0 * 32 + r) * 256 + kg + seg * 4;
            cpa16(dst, src);
        }
    };

    load_stage(0, 0);
    CP_COMMIT();

    for (int ch = 0; ch < 16; ++ch) {
        const int st = ch & 1;
        if (ch + 1 < 16) {
            load_stage(st ^ 1, ch + 1);
            CP_COMMIT();
            CP_WAIT(1);
        } else {
            CP_WAIT(0);
        }
        __syncthreads();
        const float* base = smf + st * STAGEF;
#pragma unroll
        for (int p = 0; p < 3; ++p) {
            const float* sa = base + ((p == 2) ? ARRF : 0);
            const float* sb = base + ((p == 1) ? 3 * ARRF : 2 * ARRF);
#pragma unroll
            for (int k2 = 0; k2 < 2; ++k2) {
                const int ko = k2 * 8 + lc * 2;
                float2 a0[2], a1[2];
#pragma unroll
                for (int sm = 0; sm < 2; ++sm) {
                    int rb = mw * 32 + sm * 16 + lr;
                    a0[sm] = *(const float2*)(sa + rb * STRP + ko);
                    a1[sm] = *(const float2*)(sa + (rb + 8) * STRP + ko);
                }
                float2 bf[8];
#pragma unroll
                for (int sn = 0; sn < 8; ++sn) {
                    int nb = nw * 64 + sn * 8 + lr;
                    bf[sn] = *(const float2*)(sb + nb * STRP + ko);
                }
#pragma unroll
                for (int sm = 0; sm < 2; ++sm)
#pragma unroll
                    for (int sn = 0; sn < 8; ++sn)
                        mma_tf32(acc[sm][sn], a0[sm].x, a1[sm].x,
                                 a0[sm].y, a1[sm].y, bf[sn].x, bf[sn].y);
            }
        }
        __syncthreads();
    }

#pragma unroll
    for (int sm = 0; sm < 2; ++sm) {
        int dbase = m0 + mw * 32 + sm * 16 + lr;
#pragma unroll
        for (int sn = 0; sn < 8; ++sn) {
            int n = nw * 64 + sn * 8 + 2 * lc;
            int b = b0 + (n >> 5);
            int q = n & 31;
#pragma unroll
            for (int hf = 0; hf < 2; ++hf) {
                int d   = dbase + 8 * hf;
                int c2i = (d >> 3) & 31;
                int q2  = d >> 8;
                float* o = out0 + ((b * 32 + c2i) * 32 + q2) * 256 + (d & 7) * 32 + q;
                *(float2*)o = make_float2(acc[sm][sn][2 * hf], acc[sm][sn][2 * hf + 1]);
            }
        }
    }
}

// ============================================================================
extern "C" void kernel_launch(void* const* d_in, const int* in_sizes, int n_in,
                              void* d_out, int out_size) {
    const float* inp = (const float*)d_in[0];
    const float* ctx = (const float*)d_in[1];
    const float* W   = (const float*)d_in[2];
    float* out = (float*)d_out;

    static int inited = 0;
    if (!inited) {
        cudaFuncSetAttribute(k1_mma, cudaFuncAttributeMaxDynamicSharedMemorySize, SMEM_GEMM);
        cudaFuncSetAttribute(k3_mma, cudaFuncAttributeMaxDynamicSharedMemorySize, SMEM_GEMM);
        inited = 1;
    }

    k0b_split_W<<<IDF_SZ / 32, 256>>>(W);
    k1_mma<<<dim3(32, KS1), 256, SMEM_GEMM>>>(inp);
    k2_attn<<<B_SZ * 4, 256>>>(ctx, out + WC_ELEMS);
    k3_mma<<<dim3(64, 16), 256, SMEM_GEMM>>>(out);
}

// round 8
// speedup vs baseline: 1.7801x; 1.1204x over previous
#include <cuda_runtime.h>

// Problem:
//   input   [64, 32, 32, 16, 16] f32  -> A rows [b*32+q][d], d = cl*256+hw
//   context [64, 256, 128]       f32
//   W       [8192, 256]          f32
// Outputs: wc [64,32,32,16,16] f32 (16.7M) ; attnT [64,128,32] f32 (262K)
//
// tf32 2-split (h+l), 3 MMA passes (hh, hl, lh), m16n8k8, frag-hoisted so
// each k2 half-chunk loads A/B fragments once and reuses them across passes.
// k-dim pair-permuted {k0,k4,k1,k5,k2,k6,k3,k7} -> float2 frag LDS.
// k1 splits A in-kernel from raw input. B via cp.async double-buffer.

#define B_SZ   64
#define CDF_SZ 256
#define IDF_SZ 8192
#define WC_ELEMS (B_SZ * IDF_SZ * 32)      // 16777216
#define W_ELEMS  (IDF_SZ * CDF_SZ)
#define KS1    8
#define MROWS  (B_SZ * 32)                 // 2048
#define T2_STRIDE (MROWS * CDF_SZ)         // 524288

#define STRP   24                          // smem row stride (16 data + 8 pad)
#define ARRF   (128 * STRP)                // 3072 floats per array
#define STAGEF (4 * ARRF)                  // 12288 floats per stage
#define SMEM_GEMM (2 * STAGEF * 4)         // 98304 bytes

// ---------------- device scratch ----------------
__device__ __align__(16) float g_Wh[W_ELEMS];   // [d][cperm]
__device__ __align__(16) float g_Wl[W_ELEMS];
__device__ __align__(16) float g_WTh[W_ELEMS];  // [c][dperm]
__device__ __align__(16) float g_WTl[W_ELEMS];
__device__ float g_T2p[KS1 * T2_STRIDE];        // 16 MB
__device__ __align__(16) float g_CAh[MROWS * CDF_SZ];  // [row][cperm]
__device__ __align__(16) float g_CAl[MROWS * CDF_SZ];

// ---------------- helpers ----------------
__device__ __forceinline__ float tf32r(float x) {
    unsigned u;
    asm("cvt.rna.tf32.f32 %0, %1;" : "=r"(u) : "f"(x));
    return __uint_as_float(u);
}
__device__ __forceinline__ void split2(float x, float& h, float& l) {
    h = tf32r(x);
    l = tf32r(x - h);
}
__device__ __forceinline__ void mma_tf32(float* c, float a0, float a1,
                                         float a2, float a3,
                                         float b0, float b1) {
    asm volatile(
        "mma.sync.aligned.m16n8k8.row.col.f32.tf32.tf32.f32 "
        "{%0,%1,%2,%3}, {%4,%5,%6,%7}, {%8,%9}, {%0,%1,%2,%3};"
        : "+f"(c[0]), "+f"(c[1]), "+f"(c[2]), "+f"(c[3])
        : "r"(__float_as_uint(a0)), "r"(__float_as_uint(a1)),
          "r"(__float_as_uint(a2)), "r"(__float_as_uint(a3)),
          "r"(__float_as_uint(b0)), "r"(__float_as_uint(b1)));
}
__device__ __forceinline__ unsigned smem_u32(const void* p) {
    unsigned a;
    asm("{ .reg .u64 t; cvta.to.shared.u64 t, %1; cvt.u32.u64 %0, t; }"
        : "=r"(a) : "l"(p));
    return a;
}
__device__ __forceinline__ void cpa16(unsigned dst, const float* src) {
    asm volatile("cp.async.cg.shared.global [%0], [%1], 16;"
                 :: "r"(dst), "l"(src));
}
#define CP_COMMIT() asm volatile("cp.async.commit_group;" ::: "memory")
#define CP_WAIT(N)  asm volatile("cp.async.wait_group %0;" :: "n"(N) : "memory")
__device__ __forceinline__ int permk(int k) {
    return (k & ~7) | ((k & 3) << 1) | ((k >> 2) & 1);
}
__device__ __forceinline__ void store_perm8(float* dst, const float* v) {
    *(float4*)(dst)     = make_float4(v[0], v[4], v[1], v[5]);
    *(float4*)(dst + 4) = make_float4(v[2], v[6], v[3], v[7]);
}

// ============================================================================
// k0b: split W -> native [d][cperm] and transposed [c][dperm]
// ============================================================================
__global__ __launch_bounds__(256) void k0b_split_W(const float* __restrict__ W) {
    __shared__ float tw[32 * 260];
    const int d0  = blockIdx.x * 32;
    const int tid = threadIdx.x;
    {
        int row = tid >> 3;
        int c0  = (tid & 7) * 32;
#pragma unroll
        for (int grp = 0; grp < 4; ++grp) {
            int cb = c0 + grp * 8;
            float4 v0 = *(const float4*)(W + (d0 + row) * 256 + cb);
            float4 v1 = *(const float4*)(W + (d0 + row) * 256 + cb + 4);
            float x[8] = {v0.x, v0.y, v0.z, v0.w, v1.x, v1.y, v1.z, v1.w};
            float h[8], l[8];
#pragma unroll
            for (int e = 0; e < 8; ++e) split2(x[e], h[e], l[e]);
            store_perm8(g_Wh + (d0 + row) * 256 + cb, h);
            store_perm8(g_Wl + (d0 + row) * 256 + cb, l);
            *(float4*)(tw + row * 260 + cb)     = v0;
            *(float4*)(tw + row * 260 + cb + 4) = v1;
        }
    }
    __syncthreads();
    {
        int c = tid;
#pragma unroll
        for (int jb = 0; jb < 4; ++jb) {
            float h[8], l[8];
#pragma unroll
            for (int i = 0; i < 8; ++i)
                split2(tw[(jb * 8 + i) * 260 + c], h[i], l[i]);
            int gi = c * IDF_SZ + d0 + jb * 8;
            store_perm8(g_WTh + gi, h);
            store_perm8(g_WTl + gi, l);
        }
    }
}

// ============================================================================
// k1: T2 partials. M=128(row) x N=128(c), K=1024/block (64 chunks of 16).
//   Grid (32 = 16mt x 2nt, 8 ks). 8 warps (2m x 4n), warp 64x32.
//   Frag-hoisted 3-pass: per k2 load Ah,Bh,Bl -> hh,hl; load Al -> lh.
// ============================================================================
__global__ __launch_bounds__(256, 2) void k1_mma(const float* __restrict__ inp) {
    extern __shared__ float smf[];
    const int mt = blockIdx.x >> 1, nt = blockIdx.x & 1, ks = blockIdx.y;
    const int m0 = mt * 128, n0 = nt * 128, kg0 = ks * 1024;
    const int tid = threadIdx.x, wid = tid >> 5, lane = tid & 31;
    const int mw = wid & 1, nw = wid >> 1;
    const int lr = lane >> 2, lc = lane & 3;
    const unsigned smb = smem_u32(smf);

    float acc[4][4][4];
#pragma unroll
    for (int i = 0; i < 4; ++i)
#pragma unroll
        for (int j = 0; j < 4; ++j)
#pragma unroll
            for (int e = 0; e < 4; ++e) acc[i][j][e] = 0.0f;

    const int arow = tid >> 1;
    const int ahalf = tid & 1;
    const int aR = m0 + arow;
    const int ab = aR >> 5, aq = aR & 31;

    auto load_B = [&](int st, int ch) {
        const int kg = kg0 + ch * 16;
        const unsigned sb = smb + (st * STAGEF) * 4;
#pragma unroll
        for (int it = 0; it < 4; ++it) {
            int arr = 2 + (it >> 1);
            int rem = (it & 1) * 256 + tid;
            int r = rem >> 2, seg = rem & 3;
            unsigned dst = sb + (arr * ARRF + r * STRP + seg * 4) * 4;
            const float* src = (arr == 2)
                ? g_WTh + (size_t)(n0 + r) * 8192 + kg + seg * 4
                : g_WTl + (size_t)(n0 + r) * 8192 + kg + seg * 4;
            cpa16(dst, src);
        }
    };
    auto load_A_regs = [&](int ch, float* xr) {
        const int kg = kg0 + ch * 16;
        const int cl = kg >> 8, hw = (kg & 255) + 8 * ahalf;
        const float* src = inp + (((ab * 32 + cl) * 32 + aq) << 8) + hw;
        float4 v0 = *(const float4*)(src);
        float4 v1 = *(const float4*)(src + 4);
        xr[0] = v0.x; xr[1] = v0.y; xr[2] = v0.z; xr[3] = v0.w;
        xr[4] = v1.x; xr[5] = v1.y; xr[6] = v1.z; xr[7] = v1.w;
    };

    float xr[8];
    load_A_regs(0, xr);
    load_B(0, 0);
    CP_COMMIT();

    for (int ch = 0; ch < 64; ++ch) {
        const int st = ch & 1;
        {
            float h[8], l[8];
#pragma unroll
            for (int e = 0; e < 8; ++e) split2(xr[e], h[e], l[e]);
            float* base = smf + st * STAGEF + arow * STRP + 8 * ahalf;
            store_perm8(base, h);
            store_perm8(base + ARRF, l);
        }
        if (ch + 1 < 64) {
            load_A_regs(ch + 1, xr);
            load_B(st ^ 1, ch + 1);
            CP_COMMIT();
            CP_WAIT(1);
        } else {
            CP_WAIT(0);
        }
        __syncthreads();
        const float* base = smf + st * STAGEF;
        const float* sAh = base;
        const float* sAl = base + ARRF;
        const float* sBh = base + 2 * ARRF;
        const float* sBl = base + 3 * ARRF;
#pragma unroll
        for (int k2 = 0; k2 < 2; ++k2) {
            const int ko = k2 * 8 + lc * 2;
            // B frags (h and l) once
            float2 bh[4], bl[4];
#pragma unroll
            for (int sn = 0; sn < 4; ++sn) {
                int nb = nw * 32 + sn * 8 + lr;
                bh[sn] = *(const float2*)(sBh + nb * STRP + ko);
                bl[sn] = *(const float2*)(sBl + nb * STRP + ko);
            }
            // A high frags -> passes hh, hl
            {
                float2 a0[4], a1[4];
#pragma unroll
                for (int sm = 0; sm < 4; ++sm) {
                    int rb = mw * 64 + sm * 16 + lr;
                    a0[sm] = *(const float2*)(sAh + rb * STRP + ko);
                    a1[sm] = *(const float2*)(sAh + (rb + 8) * STRP + ko);
                }
#pragma unroll
                for (int sm = 0; sm < 4; ++sm)
#pragma unroll
                    for (int sn = 0; sn < 4; ++sn) {
                        mma_tf32(acc[sm][sn], a0[sm].x, a1[sm].x,
                                 a0[sm].y, a1[sm].y, bh[sn].x, bh[sn].y);
                        mma_tf32(acc[sm][sn], a0[sm].x, a1[sm].x,
                                 a0[sm].y, a1[sm].y, bl[sn].x, bl[sn].y);
                    }
            }
            // A low frags -> pass lh
            {
                float2 a0[4], a1[4];
#pragma unroll
                for (int sm = 0; sm < 4; ++sm) {
                    int rb = mw * 64 + sm * 16 + lr;
                    a0[sm] = *(const float2*)(sAl + rb * STRP + ko);
                    a1[sm] = *(const float2*)(sAl + (rb + 8) * STRP + ko);
                }
#pragma unroll
                for (int sm = 0; sm < 4; ++sm)
#pragma unroll
                    for (int sn = 0; sn < 4; ++sn)
                        mma_tf32(acc[sm][sn], a0[sm].x, a1[sm].x,
                                 a0[sm].y, a1[sm].y, bh[sn].x, bh[sn].y);
            }
        }
        __syncthreads();
    }

    float* dst = g_T2p + (size_t)ks * T2_STRIDE;
#pragma unroll
    for (int sm = 0; sm < 4; ++sm) {
        int r = m0 + mw * 64 + sm * 16 + lr;
#pragma unroll
        for (int sn = 0; sn < 4; ++sn) {
            int c = n0 + nw * 32 + sn * 8 + 2 * lc;
            *(float2*)(dst + r * 256 + c) = make_float2(acc[sm][sn][0], acc[sm][sn][1]);
            *(float2*)(dst + (r + 8) * 256 + c) = make_float2(acc[sm][sn][2], acc[sm][sn][3]);
        }
    }
}

// ============================================================================
// k2 (4 blocks per b, 8 q-rows each, 256 threads)
// ============================================================================
#define APAD 133

__global__ __launch_bounds__(256) void k2_attn(const float* __restrict__ ctx,
                                               float* __restrict__ outAttnT) {
    __shared__ float T2s[8 * 256];
    __shared__ float attn[8 * APAD];

    const int b   = blockIdx.x >> 2;
    const int q0  = (blockIdx.x & 3) * 8;
    const int tid = threadIdx.x;

#pragma unroll
    for (int i = 0; i < 2; ++i) {
        int idx = tid + i * 256;
        int ql  = idx >> 6;
        int cc  = (idx & 63) * 4;
        const float* src = g_T2p + (b * 32 + q0 + ql) * 256 + cc;
        float4 s = *(const float4*)(src);
#pragma unroll
        for (int p = 1; p < KS1; ++p) {
            float4 t = *(const float4*)(src + (size_t)p * T2_STRIDE);
            s.x += t.x; s.y += t.y; s.z += t.z; s.w += t.w;
        }
        *(float4*)(T2s + 4 * idx) = s;
    }
    __syncthreads();

    {
        const int s = tid & 127;
        const int g = tid >> 7;
        float acc[4] = {0.f, 0.f, 0.f, 0.f};
        const float* cb = ctx + b * 32768 + s;
        const float* t2 = T2s + g * 4 * 256;
        for (int c = 0; c < 256; ++c) {
            float cv = cb[c * 128];
#pragma unroll
            for (int j = 0; j < 4; ++j)
                acc[j] += t2[j * 256 + c] * cv;
        }
#pragma unroll
        for (int j = 0; j < 4; ++j) attn[(g * 4 + j) * APAD + s] = acc[j];
    }
    __syncthreads();

    {
        const int warp = tid >> 5, lane = tid & 31;
        float v0 = attn[warp * APAD + lane];
        float v1 = attn[warp * APAD + lane + 32];
        float v2 = attn[warp * APAD + lane + 64];
        float v3 = attn[warp * APAD + lane + 96];
        float mx = fmaxf(fmaxf(v0, v1), fmaxf(v2, v3));
#pragma unroll
        for (int o = 16; o > 0; o >>= 1)
            mx = fmaxf(mx, __shfl_xor_sync(0xffffffffu, mx, o));
        float e0 = expf(v0 - mx), e1 = expf(v1 - mx);
        float e2 = expf(v2 - mx), e3 = expf(v3 - mx);
        float sm = e0 + e1 + e2 + e3;
#pragma unroll
        for (int o = 16; o > 0; o >>= 1)
            sm += __shfl_xor_sync(0xffffffffu, sm, o);
        float inv = 1.0f / sm;
        attn[warp * APAD + lane]      = e0 * inv;
        attn[warp * APAD + lane + 32] = e1 * inv;
        attn[warp * APAD + lane + 64] = e2 * inv;
        attn[warp * APAD + lane + 96] = e3 * inv;
    }
    __syncthreads();

#pragma unroll
    for (int i = 0; i < 4; ++i) {
        int idx = tid + i * 256;
        int s = idx >> 3, ql = idx & 7;
        outAttnT[b * 4096 + s * 32 + q0 + ql] = attn[ql * APAD + s];
    }

    {
        const int c = tid;
        float a2[8] = {0.f,0.f,0.f,0.f,0.f,0.f,0.f,0.f};
        const float* cb = ctx + (b * 256 + c) * 128;
        for (int s = 0; s < 128; ++s) {
            float cv = cb[s];
#pragma unroll
            for (int j = 0; j < 8; ++j)
                a2[j] += attn[j * APAD + s] * cv;
        }
        int cp = permk(c);
#pragma unroll
        for (int j = 0; j < 8; ++j) {
            float h, l;
            split2(a2[j], h, l);
            int gi = (b * 32 + q0 + j) * 256 + cp;
            g_CAh[gi] = h;
            g_CAl[gi] = l;
        }
    }
}

// ============================================================================
// k3: wc = W @ CA^T.  M=128(d) x N=128(4b x 32q), K=256 (16 chunks).
//   Frag-hoisted 3-pass like k1. 8 warps (4m x 2n), warp 32x64.
// ============================================================================
__global__ __launch_bounds__(256, 2) void k3_mma(float* __restrict__ out0) {
    extern __shared__ float smf[];
    const int m0 = blockIdx.x * 128;
    const int b0 = blockIdx.y * 4;
    const int tid = threadIdx.x, wid = tid >> 5, lane = tid & 31;
    const int mw = wid & 3, nw = wid >> 2;
    const int lr = lane >> 2, lc = lane & 3;
    const unsigned smb = smem_u32(smf);

    float acc[2][8][4];
#pragma unroll
    for (int i = 0; i < 2; ++i)
#pragma unroll
        for (int j = 0; j < 8; ++j)
#pragma unroll
            for (int e = 0; e < 4; ++e) acc[i][j][e] = 0.0f;

    auto load_stage = [&](int st, int ch) {
        const int kg = ch * 16;
        const unsigned sb = smb + (st * STAGEF) * 4;
#pragma unroll
        for (int it = 0; it < 8; ++it) {
            int arr = it >> 1;
            int rem = (it & 1) * 256 + tid;
            int r = rem >> 2, seg = rem & 3;
            unsigned dst = sb + (arr * ARRF + r * STRP + seg * 4) * 4;
            const float* src;
            if (arr == 0)      src = g_Wh  + (size_t)(m0 + r) * 256 + kg + seg * 4;
            else if (arr == 1) src = g_Wl  + (size_t)(m0 + r) * 256 + kg + seg * 4;
            else if (arr == 2) src = g_CAh + (size_t)(b0 * 32 + r) * 256 + kg + seg * 4;
            else               src = g_CAl + (size_t)(b0 * 32 + r) * 256 + kg + seg * 4;
            cpa16(dst, src);
        }
    };

    load_stage(0, 0);
    CP_COMMIT();

    for (int ch = 0; ch < 16; ++ch) {
        const int st = ch & 1;
        if (ch + 1 < 16) {
            load_stage(st ^ 1, ch + 1);
            CP_COMMIT();
            CP_WAIT(1);
        } else {
            CP_WAIT(0);
        }
        __syncthreads();
        const float* base = smf + st * STAGEF;
        const float* sAh = base;
        const float* sAl = base + ARRF;
        const float* sBh = base + 2 * ARRF;
        const float* sBl = base + 3 * ARRF;
#pragma unroll
        for (int k2 = 0; k2 < 2; ++k2) {
            const int ko = k2 * 8 + lc * 2;
            float2 bh[8], bl[8];
#pragma unroll
            for (int sn = 0; sn < 8; ++sn) {
                int nb = nw * 64 + sn * 8 + lr;
                bh[sn] = *(const float2*)(sBh + nb * STRP + ko);
                bl[sn] = *(const float2*)(sBl + nb * STRP + ko);
            }
            {
                float2 a0[2], a1[2];
#pragma unroll
                for (int sm = 0; sm < 2; ++sm) {
                    int rb = mw * 32 + sm * 16 + lr;
                    a0[sm] = *(const float2*)(sAh + rb * STRP + ko);
                    a1[sm] = *(const float2*)(sAh + (rb + 8) * STRP + ko);
                }
#pragma unroll
                for (int sm = 0; sm < 2; ++sm)
#pragma unroll
                    for (int sn = 0; sn < 8; ++sn) {
                        mma_tf32(acc[sm][sn], a0[sm].x, a1[sm].x,
                                 a0[sm].y, a1[sm].y, bh[sn].x, bh[sn].y);
                        mma_tf32(acc[sm][sn], a0[sm].x, a1[sm].x,
                                 a0[sm].y, a1[sm].y, bl[sn].x, bl[sn].y);
                    }
            }
            {
                float2 a0[2], a1[2];
#pragma unroll
                for (int sm = 0; sm < 2; ++sm) {
                    int rb = mw * 32 + sm * 16 + lr;
                    a0[sm] = *(const float2*)(sAl + rb * STRP + ko);
                    a1[sm] = *(const float2*)(sAl + (rb + 8) * STRP + ko);
                }
#pragma unroll
                for (int sm = 0; sm < 2; ++sm)
#pragma unroll
                    for (int sn = 0; sn < 8; ++sn)
                        mma_tf32(acc[sm][sn], a0[sm].x, a1[sm].x,
                                 a0[sm].y, a1[sm].y, bh[sn].x, bh[sn].y);
            }
        }
        __syncthreads();
    }

#pragma unroll
    for (int sm = 0; sm < 2; ++sm) {
        int dbase = m0 + mw * 32 + sm * 16 + lr;
#pragma unroll
        for (int sn = 0; sn < 8; ++sn) {
            int n = nw * 64 + sn * 8 + 2 * lc;
            int b = b0 + (n >> 5);
            int q = n & 31;
#pragma unroll
            for (int hf = 0; hf < 2; ++hf) {
                int d   = dbase + 8 * hf;
                int c2i = (d >> 3) & 31;
                int q2  = d >> 8;
                float* o = out0 + ((b * 32 + c2i) * 32 + q2) * 256 + (d & 7) * 32 + q;
                *(float2*)o = make_float2(acc[sm][sn][2 * hf], acc[sm][sn][2 * hf + 1]);
            }
        }
    }
}

// ============================================================================
extern "C" void kernel_launch(void* const* d_in, const int* in_sizes, int n_in,
                              void* d_out, int out_size) {
    const float* inp = (const float*)d_in[0];
    const float* ctx = (const float*)d_in[1];
    const float* W   = (const float*)d_in[2];
    float* out = (float*)d_out;

    static int inited = 0;
    if (!inited) {
        cudaFuncSetAttribute(k1_mma, cudaFuncAttributeMaxDynamicSharedMemorySize, SMEM_GEMM);
        cudaFuncSetAttribute(k3_mma, cudaFuncAttributeMaxDynamicSharedMemorySize, SMEM_GEMM);
        inited = 1;
    }

    k0b_split_W<<<IDF_SZ / 32, 256>>>(W);
    k1_mma<<<dim3(32, KS1), 256, SMEM_GEMM>>>(inp);
    k2_attn<<<B_SZ * 4, 256>>>(ctx, out + WC_ELEMS);
    k3_mma<<<dim3(64, 16), 256, SMEM_GEMM>>>(out);
}

// round 9
// speedup vs baseline: 1.8229x; 1.0240x over previous
#include <cuda_runtime.h>

// Problem:
//   input   [64, 32, 32, 16, 16] f32  -> A rows [b*32+q][d], d = cl*256+hw
//   context [64, 256, 128]       f32
//   W       [8192, 256]          f32
// Outputs: wc [64,32,32,16,16] f32 (16.7M) ; attnT [64,128,32] f32 (262K)
//
// tf32 2-split (h+l), 3 MMA passes (hh, hl, lh), m16n8k8, frag-hoisted.
// k-dim pair-permuted {k0,k4,k1,k5,k2,k6,k3,k7} -> float2 frag LDS.
// k1: 512-thread CTA, M=128 x N=256, 3-stage cp.async ring, 1 sync/chunk.
// k3: 256-thread 2-CTA/SM, 2-stage (unchanged from R8).

#define B_SZ   64
#define CDF_SZ 256
#define IDF_SZ 8192
#define WC_ELEMS (B_SZ * IDF_SZ * 32)      // 16777216
#define W_ELEMS  (IDF_SZ * CDF_SZ)
#define KS1    8
#define MROWS  (B_SZ * 32)                 // 2048
#define T2_STRIDE (MROWS * CDF_SZ)         // 524288

#define STRP   24                          // smem row stride (16 data + 8 pad)

// ---- k1 (512 thr) stage layout: Ah@0, Al@3072, Bh@6144, Bl@12288 ----
#define K1_ARRA   (128 * STRP)             // 3072 floats
#define K1_ARRB   (256 * STRP)             // 6144 floats
#define K1_STAGEF (2 * K1_ARRA + 2 * K1_ARRB)   // 18432 floats
#define K1_SMEM   (3 * K1_STAGEF * 4)      // 221184 bytes
#define K1_NCH    64

// ---- k3 (256 thr) stage layout (R8) ----
#define ARRF   (128 * STRP)                // 3072 floats per array
#define STAGEF (4 * ARRF)                  // 12288 floats per stage
#define SMEM_GEMM (2 * STAGEF * 4)         // 98304 bytes

// ---------------- device scratch ----------------
__device__ __align__(16) float g_Wh[W_ELEMS];   // [d][cperm]
__device__ __align__(16) float g_Wl[W_ELEMS];
__device__ __align__(16) float g_WTh[W_ELEMS];  // [c][dperm]
__device__ __align__(16) float g_WTl[W_ELEMS];
__device__ float g_T2p[KS1 * T2_STRIDE];        // 16 MB
__device__ __align__(16) float g_CAh[MROWS * CDF_SZ];  // [row][cperm]
__device__ __align__(16) float g_CAl[MROWS * CDF_SZ];

// ---------------- helpers ----------------
__device__ __forceinline__ float tf32r(float x) {
    unsigned u;
    asm("cvt.rna.tf32.f32 %0, %1;" : "=r"(u) : "f"(x));
    return __uint_as_float(u);
}
__device__ __forceinline__ void split2(float x, float& h, float& l) {
    h = tf32r(x);
    l = tf32r(x - h);
}
__device__ __forceinline__ void mma_tf32(float* c, float a0, float a1,
                                         float a2, float a3,
                                         float b0, float b1) {
    asm volatile(
        "mma.sync.aligned.m16n8k8.row.col.f32.tf32.tf32.f32 "
        "{%0,%1,%2,%3}, {%4,%5,%6,%7}, {%8,%9}, {%0,%1,%2,%3};"
        : "+f"(c[0]), "+f"(c[1]), "+f"(c[2]), "+f"(c[3])
        : "r"(__float_as_uint(a0)), "r"(__float_as_uint(a1)),
          "r"(__float_as_uint(a2)), "r"(__float_as_uint(a3)),
          "r"(__float_as_uint(b0)), "r"(__float_as_uint(b1)));
}
__device__ __forceinline__ unsigned smem_u32(const void* p) {
    unsigned a;
    asm("{ .reg .u64 t; cvta.to.shared.u64 t, %1; cvt.u32.u64 %0, t; }"
        : "=r"(a) : "l"(p));
    return a;
}
__device__ __forceinline__ void cpa16(unsigned dst, const float* src) {
    asm volatile("cp.async.cg.shared.global [%0], [%1], 16;"
                 :: "r"(dst), "l"(src));
}
#define CP_COMMIT() asm volatile("cp.async.commit_group;" ::: "memory")
#define CP_WAIT(N)  asm volatile("cp.async.wait_group %0;" :: "n"(N) : "memory")
__device__ __forceinline__ int permk(int k) {
    return (k & ~7) | ((k & 3) << 1) | ((k >> 2) & 1);
}
__device__ __forceinline__ void store_perm8(float* dst, const float* v) {
    *(float4*)(dst)     = make_float4(v[0], v[4], v[1], v[5]);
    *(float4*)(dst + 4) = make_float4(v[2], v[6], v[3], v[7]);
}

// ============================================================================
// k0b: split W -> native [d][cperm] and transposed [c][dperm]
// ============================================================================
__global__ __launch_bounds__(256) void k0b_split_W(const float* __restrict__ W) {
    __shared__ float tw[32 * 260];
    const int d0  = blockIdx.x * 32;
    const int tid = threadIdx.x;
    {
        int row = tid >> 3;
        int c0  = (tid & 7) * 32;
#pragma unroll
        for (int grp = 0; grp < 4; ++grp) {
            int cb = c0 + grp * 8;
            float4 v0 = *(const float4*)(W + (d0 + row) * 256 + cb);
            float4 v1 = *(const float4*)(W + (d0 + row) * 256 + cb + 4);
            float x[8] = {v0.x, v0.y, v0.z, v0.w, v1.x, v1.y, v1.z, v1.w};
            float h[8], l[8];
#pragma unroll
            for (int e = 0; e < 8; ++e) split2(x[e], h[e], l[e]);
            store_perm8(g_Wh + (d0 + row) * 256 + cb, h);
            store_perm8(g_Wl + (d0 + row) * 256 + cb, l);
            *(float4*)(tw + row * 260 + cb)     = v0;
            *(float4*)(tw + row * 260 + cb + 4) = v1;
        }
    }
    __syncthreads();
    {
        int c = tid;
#pragma unroll
        for (int jb = 0; jb < 4; ++jb) {
            float h[8], l[8];
#pragma unroll
            for (int i = 0; i < 8; ++i)
                split2(tw[(jb * 8 + i) * 260 + c], h[i], l[i]);
            int gi = c * IDF_SZ + d0 + jb * 8;
            store_perm8(g_WTh + gi, h);
            store_perm8(g_WTl + gi, l);
        }
    }
}

// ============================================================================
// k1: T2 partials. 512 threads, M=128(row) x N=256(c), K=1024/block.
//   Grid (16 mt, 8 ks). 16 warps (2m x 8n), warp 64x32.
//   3-stage cp.async ring, 1 __syncthreads per chunk.
//   A: raw input LDG -> reg split -> STS (threads 0-255).
//   B: cp.async (all threads, 4 cpa16 each).
// ============================================================================
__global__ __launch_bounds__(512, 1) void k1_mma(const float* __restrict__ inp) {
    extern __shared__ float smf[];
    const int mt = blockIdx.x, ks = blockIdx.y;
    const int m0 = mt * 128, kg0 = ks * 1024;
    const int tid = threadIdx.x, wid = tid >> 5, lane = tid & 31;
    const int mw = wid & 1, nw = wid >> 1;          // 2m x 8n
    const int lr = lane >> 2, lc = lane & 3;
    const unsigned smb = smem_u32(smf);

    float acc[4][4][4];
#pragma unroll
    for (int i = 0; i < 4; ++i)
#pragma unroll
        for (int j = 0; j < 4; ++j)
#pragma unroll
            for (int e = 0; e < 4; ++e) acc[i][j][e] = 0.0f;

    // A loader geometry (threads 0-255): row tid>>1, half tid&1
    const int arow = tid >> 1;
    const int ahalf = tid & 1;
    const int aR = m0 + arow;
    const int ab = aR >> 5, aq = aR & 31;

    auto load_A_regs = [&](int ch, float* xr) {
        if (tid < 256) {
            const int kg = kg0 + ch * 16;
            const int cl = kg >> 8, hw = (kg & 255) + 8 * ahalf;
            const float* src = inp + (((ab * 32 + cl) * 32 + aq) << 8) + hw;
            float4 v0 = *(const float4*)(src);
            float4 v1 = *(const float4*)(src + 4);
            xr[0] = v0.x; xr[1] = v0.y; xr[2] = v0.z; xr[3] = v0.w;
            xr[4] = v1.x; xr[5] = v1.y; xr[6] = v1.z; xr[7] = v1.w;
        }
    };
    auto sts_A = [&](int st, const float* xr) {
        if (tid < 256) {
            float h[8], l[8];
#pragma unroll
            for (int e = 0; e < 8; ++e) split2(xr[e], h[e], l[e]);
            float* base = smf + st * K1_STAGEF + arow * STRP + 8 * ahalf;
            store_perm8(base, h);
            store_perm8(base + K1_ARRA, l);
        }
    };
    // B: 2 arrays x 256 rows x 4 segs = 2048 float4 / 512 thr = 4 each
    auto load_B = [&](int st, int ch) {
        const int kg = kg0 + ch * 16;
        const unsigned sb = smb + (st * K1_STAGEF) * 4;
#pragma unroll
        for (int it = 0; it < 4; ++it) {
            int arr = it >> 1;
            int rem = (it & 1) * 512 + tid;      // 0..1023
            int r = rem >> 2, seg = rem & 3;
            unsigned dst = sb + (2 * K1_ARRA + arr * K1_ARRB + r * STRP + seg * 4) * 4;
            const float* src = (arr == 0)
                ? g_WTh + (size_t)r * 8192 + kg + seg * 4
                : g_WTl + (size_t)r * 8192 + kg + seg * 4;
            cpa16(dst, src);
        }
    };

    float xr[8];
    // prologue
    load_A_regs(0, xr);
    sts_A(0, xr);
    load_A_regs(1, xr);
    load_B(0, 0); CP_COMMIT();
    load_B(1, 1); CP_COMMIT();

    for (int ch = 0; ch < K1_NCH; ++ch) {
        const int st = ch % 3;
        CP_WAIT(1);
        __syncthreads();
        if (ch + 1 < K1_NCH) sts_A((ch + 1) % 3, xr);
        if (ch + 2 < K1_NCH) {
            load_A_regs(ch + 2, xr);
            load_B((ch + 2) % 3, ch + 2);
        }
        CP_COMMIT();

        const float* base = smf + st * K1_STAGEF;
        const float* sAh = base;
        const float* sAl = base + K1_ARRA;
        const float* sBh = base + 2 * K1_ARRA;
        const float* sBl = base + 2 * K1_ARRA + K1_ARRB;
#pragma unroll
        for (int k2 = 0; k2 < 2; ++k2) {
            const int ko = k2 * 8 + lc * 2;
            float2 bh[4], bl[4];
#pragma unroll
            for (int sn = 0; sn < 4; ++sn) {
                int nb = nw * 32 + sn * 8 + lr;
                bh[sn] = *(const float2*)(sBh + nb * STRP + ko);
                bl[sn] = *(const float2*)(sBl + nb * STRP + ko);
            }
            {
                float2 a0[4], a1[4];
#pragma unroll
                for (int sm = 0; sm < 4; ++sm) {
                    int rb = mw * 64 + sm * 16 + lr;
                    a0[sm] = *(const float2*)(sAh + rb * STRP + ko);
                    a1[sm] = *(const float2*)(sAh + (rb + 8) * STRP + ko);
                }
#pragma unroll
                for (int sm = 0; sm < 4; ++sm)
#pragma unroll
                    for (int sn = 0; sn < 4; ++sn) {
                        mma_tf32(acc[sm][sn], a0[sm].x, a1[sm].x,
                                 a0[sm].y, a1[sm].y, bh[sn].x, bh[sn].y);
                        mma_tf32(acc[sm][sn], a0[sm].x, a1[sm].x,
                                 a0[sm].y, a1[sm].y, bl[sn].x, bl[sn].y);
                    }
            }
            {
                float2 a0[4], a1[4];
#pragma unroll
                for (int sm = 0; sm < 4; ++sm) {
                    int rb = mw * 64 + sm * 16 + lr;
                    a0[sm] = *(const float2*)(sAl + rb * STRP + ko);
                    a1[sm] = *(const float2*)(sAl + (rb + 8) * STRP + ko);
                }
#pragma unroll
                for (int sm = 0; sm < 4; ++sm)
#pragma unroll
                    for (int sn = 0; sn < 4; ++sn)
                        mma_tf32(acc[sm][sn], a0[sm].x, a1[sm].x,
                                 a0[sm].y, a1[sm].y, bh[sn].x, bh[sn].y);
            }
        }
        __syncthreads();   // protects stage st for the STS/cp of iteration ch+... (ring WAR)
    }

    float* dst = g_T2p + (size_t)ks * T2_STRIDE;
#pragma unroll
    for (int sm = 0; sm < 4; ++sm) {
        int r = m0 + mw * 64 + sm * 16 + lr;
#pragma unroll
        for (int sn = 0; sn < 4; ++sn) {
            int c = nw * 32 + sn * 8 + 2 * lc;
            *(float2*)(dst + r * 256 + c) = make_float2(acc[sm][sn][0], acc[sm][sn][1]);
            *(float2*)(dst + (r + 8) * 256 + c) = make_float2(acc[sm][sn][2], acc[sm][sn][3]);
        }
    }
}

// ============================================================================
// k2 (4 blocks per b, 8 q-rows each, 256 threads)
// ============================================================================
#define APAD 133

__global__ __launch_bounds__(256) void k2_attn(const float* __restrict__ ctx,
                                               float* __restrict__ outAttnT) {
    __shared__ float T2s[8 * 256];
    __shared__ float attn[8 * APAD];

    const int b   = blockIdx.x >> 2;
    const int q0  = (blockIdx.x & 3) * 8;
    const int tid = threadIdx.x;

#pragma unroll
    for (int i = 0; i < 2; ++i) {
        int idx = tid + i * 256;
        int ql  = idx >> 6;
        int cc  = (idx & 63) * 4;
        const float* src = g_T2p + (b * 32 + q0 + ql) * 256 + cc;
        float4 s = *(const float4*)(src);
#pragma unroll
        for (int p = 1; p < KS1; ++p) {
            float4 t = *(const float4*)(src + (size_t)p * T2_STRIDE);
            s.x += t.x; s.y += t.y; s.z += t.z; s.w += t.w;
        }
        *(float4*)(T2s + 4 * idx) = s;
    }
    __syncthreads();

    {
        const int s = tid & 127;
        const int g = tid >> 7;
        float acc[4] = {0.f, 0.f, 0.f, 0.f};
        const float* cb = ctx + b * 32768 + s;
        const float* t2 = T2s + g * 4 * 256;
        for (int c = 0; c < 256; ++c) {
            float cv = cb[c * 128];
#pragma unroll
            for (int j = 0; j < 4; ++j)
                acc[j] += t2[j * 256 + c] * cv;
        }
#pragma unroll
        for (int j = 0; j < 4; ++j) attn[(g * 4 + j) * APAD + s] = acc[j];
    }
    __syncthreads();

    {
        const int warp = tid >> 5, lane = tid & 31;
        float v0 = attn[warp * APAD + lane];
        float v1 = attn[warp * APAD + lane + 32];
        float v2 = attn[warp * APAD + lane + 64];
        float v3 = attn[warp * APAD + lane + 96];
        float mx = fmaxf(fmaxf(v0, v1), fmaxf(v2, v3));
#pragma unroll
        for (int o = 16; o > 0; o >>= 1)
            mx = fmaxf(mx, __shfl_xor_sync(0xffffffffu, mx, o));
        float e0 = expf(v0 - mx), e1 = expf(v1 - mx);
        float e2 = expf(v2 - mx), e3 = expf(v3 - mx);
        float sm = e0 + e1 + e2 + e3;
#pragma unroll
        for (int o = 16; o > 0; o >>= 1)
            sm += __shfl_xor_sync(0xffffffffu, sm, o);
        float inv = 1.0f / sm;
        attn[warp * APAD + lane]      = e0 * inv;
        attn[warp * APAD + lane + 32] = e1 * inv;
        attn[warp * APAD + lane + 64] = e2 * inv;
        attn[warp * APAD + lane + 96] = e3 * inv;
    }
    __syncthreads();

#pragma unroll
    for (int i = 0; i < 4; ++i) {
        int idx = tid + i * 256;
        int s = idx >> 3, ql = idx & 7;
        outAttnT[b * 4096 + s * 32 + q0 + ql] = attn[ql * APAD + s];
    }

    {
        const int c = tid;
        float a2[8] = {0.f,0.f,0.f,0.f,0.f,0.f,0.f,0.f};
        const float* cb = ctx + (b * 256 + c) * 128;
        for (int s = 0; s < 128; ++s) {
            float cv = cb[s];
#pragma unroll
            for (int j = 0; j < 8; ++j)
                a2[j] += attn[j * APAD + s] * cv;
        }
        int cp = permk(c);
#pragma unroll
        for (int j = 0; j < 8; ++j) {
            float h, l;
            split2(a2[j], h, l);
            int gi = (b * 32 + q0 + j) * 256 + cp;
            g_CAh[gi] = h;
            g_CAl[gi] = l;
        }
    }
}

// ============================================================================
// k3: wc = W @ CA^T.  M=128(d) x N=128(4b x 32q), K=256 (16 chunks).
//   Frag-hoisted 3-pass. 8 warps (4m x 2n), warp 32x64. 2-stage, 2-CTA/SM.
// ============================================================================
__global__ __launch_bounds__(256, 2) void k3_mma(float* __restrict__ out0) {
    extern __shared__ float smf[];
    const int m0 = blockIdx.x * 128;
    const int b0 = blockIdx.y * 4;
    const int tid = threadIdx.x, wid = tid >> 5, lane = tid & 31;
    const int mw = wid & 3, nw = wid >> 2;
    const int lr = lane >> 2, lc = lane & 3;
    const unsigned smb = smem_u32(smf);

    float acc[2][8][4];
#pragma unroll
    for (int i = 0; i < 2; ++i)
#pragma unroll
        for (int j = 0; j < 8; ++j)
#pragma unroll
            for (int e = 0; e < 4; ++e) acc[i][j][e] = 0.0f;

    auto load_stage = [&](int st, int ch) {
        const int kg = ch * 16;
        const unsigned sb = smb + (st * STAGEF) * 4;
#pragma unroll
        for (int it = 0; it < 8; ++it) {
            int arr = it >> 1;
            int rem = (it & 1) * 256 + tid;
            int r = rem >> 2, seg = rem & 3;
            unsigned dst = sb + (arr * ARRF + r * STRP + seg * 4) * 4;
            const float* src;
            if (arr == 0)      src = g_Wh  + (size_t)(m0 + r) * 256 + kg + seg * 4;
            else if (arr == 1) src = g_Wl  + (size_t)(m0 + r) * 256 + kg + seg * 4;
            else if (arr == 2) src = g_CAh + (size_t)(b0 * 32 + r) * 256 + kg + seg * 4;
            else               src = g_CAl + (size_t)(b0 * 32 + r) * 256 + kg + seg * 4;
            cpa16(dst, src);
        }
    };

    load_stage(0, 0);
    CP_COMMIT();

    for (int ch = 0; ch < 16; ++ch) {
        const int st = ch & 1;
        if (ch + 1 < 16) {
            load_stage(st ^ 1, ch + 1);
            CP_COMMIT();
            CP_WAIT(1);
        } else {
            CP_WAIT(0);
        }
        __syncthreads();
        const float* base = smf + st * STAGEF;
        const float* sAh = base;
        const float* sAl = base + ARRF;
        const float* sBh = base + 2 * ARRF;
        const float* sBl = base + 3 * ARRF;
#pragma unroll
        for (int k2 = 0; k2 < 2; ++k2) {
            const int ko = k2 * 8 + lc * 2;
            float2 bh[8], bl[8];
#pragma unroll
            for (int sn = 0; sn < 8; ++sn) {
                int nb = nw * 64 + sn * 8 + lr;
                bh[sn] = *(const float2*)(sBh + nb * STRP + ko);
                bl[sn] = *(const float2*)(sBl + nb * STRP + ko);
            }
            {
                float2 a0[2], a1[2];
#pragma unroll
                for (int sm = 0; sm < 2; ++sm) {
                    int rb = mw * 32 + sm * 16 + lr;
                    a0[sm] = *(const float2*)(sAh + rb * STRP + ko);
                    a1[sm] = *(const float2*)(sAh + (rb + 8) * STRP + ko);
                }
#pragma unroll
                for (int sm = 0; sm < 2; ++sm)
#pragma unroll
                    for (int sn = 0; sn < 8; ++sn) {
                        mma_tf32(acc[sm][sn], a0[sm].x, a1[sm].x,
                                 a0[sm].y, a1[sm].y, bh[sn].x, bh[sn].y);
                        mma_tf32(acc[sm][sn], a0[sm].x, a1[sm].x,
                                 a0[sm].y, a1[sm].y, bl[sn].x, bl[sn].y);
                    }
            }
            {
                float2 a0[2], a1[2];
#pragma unroll
                for (int sm = 0; sm < 2; ++sm) {
                    int rb = mw * 32 + sm * 16 + lr;
                    a0[sm] = *(const float2*)(sAl + rb * STRP + ko);
                    a1[sm] = *(const float2*)(sAl + (rb + 8) * STRP + ko);
                }
#pragma unroll
                for (int sm = 0; sm < 2; ++sm)
#pragma unroll
                    for (int sn = 0; sn < 8; ++sn)
                        mma_tf32(acc[sm][sn], a0[sm].x, a1[sm].x,
                                 a0[sm].y, a1[sm].y, bh[sn].x, bh[sn].y);
            }
        }
        __syncthreads();
    }

#pragma unroll
    for (int sm = 0; sm < 2; ++sm) {
        int dbase = m0 + mw * 32 + sm * 16 + lr;
#pragma unroll
        for (int sn = 0; sn < 8; ++sn) {
            int n = nw * 64 + sn * 8 + 2 * lc;
            int b = b0 + (n >> 5);
            int q = n & 31;
#pragma unroll
            for (int hf = 0; hf < 2; ++hf) {
                int d   = dbase + 8 * hf;
                int c2i = (d >> 3) & 31;
                int q2  = d >> 8;
                float* o = out0 + ((b * 32 + c2i) * 32 + q2) * 256 + (d & 7) * 32 + q;
                *(float2*)o = make_float2(acc[sm][sn][2 * hf], acc[sm][sn][2 * hf + 1]);
            }
        }
    }
}

// ============================================================================
extern "C" void kernel_launch(void* const* d_in, const int* in_sizes, int n_in,
                              void* d_out, int out_size) {
    const float* inp = (const float*)d_in[0];
    const float* ctx = (const float*)d_in[1];
    const float* W   = (const float*)d_in[2];
    float* out = (float*)d_out;

    static int inited = 0;
    if (!inited) {
        cudaFuncSetAttribute(k1_mma, cudaFuncAttributeMaxDynamicSharedMemorySize, K1_SMEM);
        cudaFuncSetAttribute(k3_mma, cudaFuncAttributeMaxDynamicSharedMemorySize, SMEM_GEMM);
        inited = 1;
    }

    k0b_split_W<<<IDF_SZ / 32, 256>>>(W);
    k1_mma<<<dim3(16, KS1), 512, K1_SMEM>>>(inp);
    k2_attn<<<B_SZ * 4, 256>>>(ctx, out + WC_ELEMS);
    k3_mma<<<dim3(64, 16), 256, SMEM_GEMM>>>(out);
}

// round 10
// speedup vs baseline: 2.3149x; 1.2699x over previous
#include <cuda_runtime.h>

// Problem:
//   input   [64, 32, 32, 16, 16] f32  -> A rows [b*32+q][d], d = cl*256+hw
//   context [64, 256, 128]       f32
//   W       [8192, 256]          f32
// Outputs: wc [64,32,32,16,16] f32 (16.7M) ; attnT [64,128,32] f32 (262K)
//
// tf32 2-split (h+l), m16n8k8.
// k1: 3 passes (hh, hl, lh) — softmax path needs full precision.
// k3: 2 passes (Wh*CAh, Wh*CAl) — direct-output rel tolerance allows it.
// k-dim pair-permuted {k0,k4,k1,k5,k2,k6,k3,k7} -> float2 frag LDS.
// k2: smem-staged ctx (pad-129, conflict-free both directions).

#define B_SZ   64
#define CDF_SZ 256
#define IDF_SZ 8192
#define WC_ELEMS (B_SZ * IDF_SZ * 32)      // 16777216
#define W_ELEMS  (IDF_SZ * CDF_SZ)
#define KS1    8
#define MROWS  (B_SZ * 32)                 // 2048
#define T2_STRIDE (MROWS * CDF_SZ)         // 524288

#define STRP   24                          // smem row stride (16 data + 8 pad)

// ---- k1 (512 thr) stage layout: Ah@0, Al@3072, Bh@6144, Bl@12288 ----
#define K1_ARRA   (128 * STRP)             // 3072 floats
#define K1_ARRB   (256 * STRP)             // 6144 floats
#define K1_STAGEF (2 * K1_ARRA + 2 * K1_ARRB)   // 18432 floats
#define K1_SMEM   (3 * K1_STAGEF * 4)      // 221184 bytes
#define K1_NCH    64

// ---- k3 (256 thr): 3 arrays (Wh, CAh, CAl) ----
#define ARRF    (128 * STRP)               // 3072 floats per array
#define STAGEF3 (3 * ARRF)                 // 9216 floats per stage
#define SMEM_K3 (2 * STAGEF3 * 4)          // 73728 bytes

// ---- k2 smem ----
#define CPAD  129
#define APAD2 133
#define K2_CTXF  (256 * CPAD)                       // 33024
#define K2_T2F   (16 * 256)                         // 4096
#define K2_ATTNF (16 * APAD2)                       // 2128
#define K2_SMEM  ((K2_CTXF + K2_T2F + K2_ATTNF) * 4)  // 156992 bytes

// ---------------- device scratch ----------------
__device__ __align__(16) float g_Wh[W_ELEMS];   // [d][cperm]
__device__ __align__(16) float g_WTh[W_ELEMS];  // [c][dperm]
__device__ __align__(16) float g_WTl[W_ELEMS];
__device__ float g_T2p[KS1 * T2_STRIDE];        // 16 MB
__device__ __align__(16) float g_CAh[MROWS * CDF_SZ];  // [row][cperm]
__device__ __align__(16) float g_CAl[MROWS * CDF_SZ];

// ---------------- helpers ----------------
__device__ __forceinline__ float tf32r(float x) {
    unsigned u;
    asm("cvt.rna.tf32.f32 %0, %1;" : "=r"(u) : "f"(x));
    return __uint_as_float(u);
}
__device__ __forceinline__ void split2(float x, float& h, float& l) {
    h = tf32r(x);
    l = tf32r(x - h);
}
__device__ __forceinline__ void mma_tf32(float* c, float a0, float a1,
                                         float a2, float a3,
                                         float b0, float b1) {
    asm volatile(
        "mma.sync.aligned.m16n8k8.row.col.f32.tf32.tf32.f32 "
        "{%0,%1,%2,%3}, {%4,%5,%6,%7}, {%8,%9}, {%0,%1,%2,%3};"
        : "+f"(c[0]), "+f"(c[1]), "+f"(c[2]), "+f"(c[3])
        : "r"(__float_as_uint(a0)), "r"(__float_as_uint(a1)),
          "r"(__float_as_uint(a2)), "r"(__float_as_uint(a3)),
          "r"(__float_as_uint(b0)), "r"(__float_as_uint(b1)));
}
__device__ __forceinline__ unsigned smem_u32(const void* p) {
    unsigned a;
    asm("{ .reg .u64 t; cvta.to.shared.u64 t, %1; cvt.u32.u64 %0, t; }"
        : "=r"(a) : "l"(p));
    return a;
}
__device__ __forceinline__ void cpa16(unsigned dst, const float* src) {
    asm volatile("cp.async.cg.shared.global [%0], [%1], 16;"
                 :: "r"(dst), "l"(src));
}
#define CP_COMMIT() asm volatile("cp.async.commit_group;" ::: "memory")
#define CP_WAIT(N)  asm volatile("cp.async.wait_group %0;" :: "n"(N) : "memory")
__device__ __forceinline__ int permk(int k) {
    return (k & ~7) | ((k & 3) << 1) | ((k >> 2) & 1);
}
__device__ __forceinline__ void store_perm8(float* dst, const float* v) {
    *(float4*)(dst)     = make_float4(v[0], v[4], v[1], v[5]);
    *(float4*)(dst + 4) = make_float4(v[2], v[6], v[3], v[7]);
}

// ============================================================================
// k0b: split W -> native high [d][cperm] and transposed h/l [c][dperm]
// ============================================================================
__global__ __launch_bounds__(256) void k0b_split_W(const float* __restrict__ W) {
    __shared__ float tw[32 * 260];
    const int d0  = blockIdx.x * 32;
    const int tid = threadIdx.x;
    {
        int row = tid >> 3;
        int c0  = (tid & 7) * 32;
#pragma unroll
        for (int grp = 0; grp < 4; ++grp) {
            int cb = c0 + grp * 8;
            float4 v0 = *(const float4*)(W + (d0 + row) * 256 + cb);
            float4 v1 = *(const float4*)(W + (d0 + row) * 256 + cb + 4);
            float x[8] = {v0.x, v0.y, v0.z, v0.w, v1.x, v1.y, v1.z, v1.w};
            float h[8], l[8];
#pragma unroll
            for (int e = 0; e < 8; ++e) split2(x[e], h[e], l[e]);
            store_perm8(g_Wh + (d0 + row) * 256 + cb, h);
            *(float4*)(tw + row * 260 + cb)     = v0;
            *(float4*)(tw + row * 260 + cb + 4) = v1;
        }
    }
    __syncthreads();
    {
        int c = tid;
#pragma unroll
        for (int jb = 0; jb < 4; ++jb) {
            float h[8], l[8];
#pragma unroll
            for (int i = 0; i < 8; ++i)
                split2(tw[(jb * 8 + i) * 260 + c], h[i], l[i]);
            int gi = c * IDF_SZ + d0 + jb * 8;
            store_perm8(g_WTh + gi, h);
            store_perm8(g_WTl + gi, l);
        }
    }
}

// ============================================================================
// k1: T2 partials. 512 threads, M=128(row) x N=256(c), K=1024/block.
//   Grid (16 mt, 8 ks). 16 warps (2m x 8n), warp 64x32.
//   3-stage cp.async ring, 1 __syncthreads per chunk. 3-pass tf32.
// ============================================================================
__global__ __launch_bounds__(512, 1) void k1_mma(const float* __restrict__ inp) {
    extern __shared__ float smf[];
    const int mt = blockIdx.x, ks = blockIdx.y;
    const int m0 = mt * 128, kg0 = ks * 1024;
    const int tid = threadIdx.x, wid = tid >> 5, lane = tid & 31;
    const int mw = wid & 1, nw = wid >> 1;
    const int lr = lane >> 2, lc = lane & 3;
    const unsigned smb = smem_u32(smf);

    float acc[4][4][4];
#pragma unroll
    for (int i = 0; i < 4; ++i)
#pragma unroll
        for (int j = 0; j < 4; ++j)
#pragma unroll
            for (int e = 0; e < 4; ++e) acc[i][j][e] = 0.0f;

    const int arow = tid >> 1;
    const int ahalf = tid & 1;
    const int aR = m0 + arow;
    const int ab = aR >> 5, aq = aR & 31;

    auto load_A_regs = [&](int ch, float* xr) {
        if (tid < 256) {
            const int kg = kg0 + ch * 16;
            const int cl = kg >> 8, hw = (kg & 255) + 8 * ahalf;
            const float* src = inp + (((ab * 32 + cl) * 32 + aq) << 8) + hw;
            float4 v0 = *(const float4*)(src);
            float4 v1 = *(const float4*)(src + 4);
            xr[0] = v0.x; xr[1] = v0.y; xr[2] = v0.z; xr[3] = v0.w;
            xr[4] = v1.x; xr[5] = v1.y; xr[6] = v1.z; xr[7] = v1.w;
        }
    };
    auto sts_A = [&](int st, const float* xr) {
        if (tid < 256) {
            float h[8], l[8];
#pragma unroll
            for (int e = 0; e < 8; ++e) split2(xr[e], h[e], l[e]);
            float* base = smf + st * K1_STAGEF + arow * STRP + 8 * ahalf;
            store_perm8(base, h);
            store_perm8(base + K1_ARRA, l);
        }
    };
    auto load_B = [&](int st, int ch) {
        const int kg = kg0 + ch * 16;
        const unsigned sb = smb + (st * K1_STAGEF) * 4;
#pragma unroll
        for (int it = 0; it < 4; ++it) {
            int arr = it >> 1;
            int rem = (it & 1) * 512 + tid;
            int r = rem >> 2, seg = rem & 3;
            unsigned dst = sb + (2 * K1_ARRA + arr * K1_ARRB + r * STRP + seg * 4) * 4;
            const float* src = (arr == 0)
                ? g_WTh + (size_t)r * 8192 + kg + seg * 4
                : g_WTl + (size_t)r * 8192 + kg + seg * 4;
            cpa16(dst, src);
        }
    };

    float xr[8];
    load_A_regs(0, xr);
    sts_A(0, xr);
    load_A_regs(1, xr);
    load_B(0, 0); CP_COMMIT();
    load_B(1, 1); CP_COMMIT();

    for (int ch = 0; ch < K1_NCH; ++ch) {
        const int st = ch % 3;
        CP_WAIT(1);
        __syncthreads();
        if (ch + 1 < K1_NCH) sts_A((ch + 1) % 3, xr);
        if (ch + 2 < K1_NCH) {
            load_A_regs(ch + 2, xr);
            load_B((ch + 2) % 3, ch + 2);
        }
        CP_COMMIT();

        const float* base = smf + st * K1_STAGEF;
        const float* sAh = base;
        const float* sAl = base + K1_ARRA;
        const float* sBh = base + 2 * K1_ARRA;
        const float* sBl = base + 2 * K1_ARRA + K1_ARRB;
#pragma unroll
        for (int k2 = 0; k2 < 2; ++k2) {
            const int ko = k2 * 8 + lc * 2;
            float2 bh[4], bl[4];
#pragma unroll
            for (int sn = 0; sn < 4; ++sn) {
                int nb = nw * 32 + sn * 8 + lr;
                bh[sn] = *(const float2*)(sBh + nb * STRP + ko);
                bl[sn] = *(const float2*)(sBl + nb * STRP + ko);
            }
            {
                float2 a0[4], a1[4];
#pragma unroll
                for (int sm = 0; sm < 4; ++sm) {
                    int rb = mw * 64 + sm * 16 + lr;
                    a0[sm] = *(const float2*)(sAh + rb * STRP + ko);
                    a1[sm] = *(const float2*)(sAh + (rb + 8) * STRP + ko);
                }
#pragma unroll
                for (int sm = 0; sm < 4; ++sm)
#pragma unroll
                    for (int sn = 0; sn < 4; ++sn) {
                        mma_tf32(acc[sm][sn], a0[sm].x, a1[sm].x,
                                 a0[sm].y, a1[sm].y, bh[sn].x, bh[sn].y);
                        mma_tf32(acc[sm][sn], a0[sm].x, a1[sm].x,
                                 a0[sm].y, a1[sm].y, bl[sn].x, bl[sn].y);
                    }
            }
            {
                float2 a0[4], a1[4];
#pragma unroll
                for (int sm = 0; sm < 4; ++sm) {
                    int rb = mw * 64 + sm * 16 + lr;
                    a0[sm] = *(const float2*)(sAl + rb * STRP + ko);
                    a1[sm] = *(const float2*)(sAl + (rb + 8) * STRP + ko);
                }
#pragma unroll
                for (int sm = 0; sm < 4; ++sm)
#pragma unroll
                    for (int sn = 0; sn < 4; ++sn)
                        mma_tf32(acc[sm][sn], a0[sm].x, a1[sm].x,
                                 a0[sm].y, a1[sm].y, bh[sn].x, bh[sn].y);
            }
        }
        __syncthreads();
    }

    float* dst = g_T2p + (size_t)ks * T2_STRIDE;
#pragma unroll
    for (int sm = 0; sm < 4; ++sm) {
        int r = m0 + mw * 64 + sm * 16 + lr;
#pragma unroll
        for (int sn = 0; sn < 4; ++sn) {
            int c = nw * 32 + sn * 8 + 2 * lc;
            *(float2*)(dst + r * 256 + c) = make_float2(acc[sm][sn][0], acc[sm][sn][1]);
            *(float2*)(dst + (r + 8) * 256 + c) = make_float2(acc[sm][sn][2], acc[sm][sn][3]);
        }
    }
}

// ============================================================================
// k2 (2 blocks per b, 16 q-rows each, 256 threads):
//   stage full per-b ctx tile in smem (pad-129: conflict-free for both the
//   thread-per-s logits loop and the thread-per-c CA loop).
// ============================================================================
__global__ __launch_bounds__(256) void k2_attn(const float* __restrict__ ctx,
                                               float* __restrict__ outAttnT) {
    extern __shared__ float s2[];
    float* ctxs = s2;                    // 256 x CPAD
    float* T2s  = s2 + K2_CTXF;          // 16 x 256
    float* attn = T2s + K2_T2F;          // 16 x APAD2

    const int b   = blockIdx.x >> 1;
    const int q0  = (blockIdx.x & 1) * 16;
    const int tid = threadIdx.x;

    // stage ctx[b]: 256c x 128s, coalesced LDG float4 -> padded smem
    {
        const float* cb = ctx + b * 32768;
#pragma unroll
        for (int i = 0; i < 32; ++i) {
            int idx = tid + i * 256;            // 0..8191 float4s
            int c = idx >> 5, s4 = (idx & 31) * 4;
            float4 v = *(const float4*)(cb + c * 128 + s4);
            float* d = ctxs + c * CPAD + s4;
            d[0] = v.x; d[1] = v.y; d[2] = v.z; d[3] = v.w;
        }
    }
    // reduce T2 partials for 16 q rows (4096 floats = 1024 float4)
#pragma unroll
    for (int i = 0; i < 4; ++i) {
        int idx = tid + i * 256;                // 0..1023
        int ql  = idx >> 6;
        int cc  = (idx & 63) * 4;
        const float* src = g_T2p + (b * 32 + q0 + ql) * 256 + cc;
        float4 s = *(const float4*)(src);
#pragma unroll
        for (int p = 1; p < KS1; ++p) {
            float4 t = *(const float4*)(src + (size_t)p * T2_STRIDE);
            s.x += t.x; s.y += t.y; s.z += t.z; s.w += t.w;
        }
        *(float4*)(T2s + ql * 256 + cc) = s;
    }
    __syncthreads();

    // logits: thread owns s; g = upper/lower 8 q rows
    {
        const int s = tid & 127;
        const int g = tid >> 7;
        float acc[8];
#pragma unroll
        for (int j = 0; j < 8; ++j) acc[j] = 0.0f;
        const float* t2 = T2s + g * 8 * 256;
        for (int c = 0; c < 256; ++c) {
            float cv = ctxs[c * CPAD + s];
#pragma unroll
            for (int j = 0; j < 8; ++j)
                acc[j] += t2[j * 256 + c] * cv;
        }
#pragma unroll
        for (int j = 0; j < 8; ++j) attn[(g * 8 + j) * APAD2 + s] = acc[j];
    }
    __syncthreads();

    // softmax: 8 warps x 2 rows
    {
        const int warp = tid >> 5, lane = tid & 31;
#pragma unroll
        for (int r = 0; r < 2; ++r) {
            int q = warp * 2 + r;
            float v0 = attn[q * APAD2 + lane];
            float v1 = attn[q * APAD2 + lane + 32];
            float v2 = attn[q * APAD2 + lane + 64];
            float v3 = attn[q * APAD2 + lane + 96];
            float mx = fmaxf(fmaxf(v0, v1), fmaxf(v2, v3));
#pragma unroll
            for (int o = 16; o > 0; o >>= 1)
                mx = fmaxf(mx, __shfl_xor_sync(0xffffffffu, mx, o));
            float e0 = expf(v0 - mx), e1 = expf(v1 - mx);
            float e2 = expf(v2 - mx), e3 = expf(v3 - mx);
            float sm = e0 + e1 + e2 + e3;
#pragma unroll
            for (int o = 16; o > 0; o >>= 1)
                sm += __shfl_xor_sync(0xffffffffu, sm, o);
            float inv = 1.0f / sm;
            attn[q * APAD2 + lane]      = e0 * inv;
            attn[q * APAD2 + lane + 32] = e1 * inv;
            attn[q * APAD2 + lane + 64] = e2 * inv;
            attn[q * APAD2 + lane + 96] = e3 * inv;
        }
    }
    __syncthreads();

    // attnT output: [b][s][q0+ql], 2048 entries
#pragma unroll
    for (int i = 0; i < 8; ++i) {
        int idx = tid + i * 256;
        int s = idx >> 4, ql = idx & 15;
        outAttnT[b * 4096 + s * 32 + q0 + ql] = attn[ql * APAD2 + s];
    }

    // CA: thread owns c; ctx from smem (stride CPAD -> conflict-free)
    {
        const int c = tid;
        float a2[16];
#pragma unroll
        for (int j = 0; j < 16; ++j) a2[j] = 0.0f;
        const float* cr = ctxs + c * CPAD;
        for (int s = 0; s < 128; ++s) {
            float cv = cr[s];
#pragma unroll
            for (int j = 0; j < 16; ++j)
                a2[j] += attn[j * APAD2 + s] * cv;
        }
        int cp = permk(c);
#pragma unroll
        for (int j = 0; j < 16; ++j) {
            float h, l;
            split2(a2[j], h, l);
            int gi = (b * 32 + q0 + j) * 256 + cp;
            g_CAh[gi] = h;
            g_CAl[gi] = l;
        }
    }
}

// ============================================================================
// k3: wc = Wh @ (CAh + CAl)^T.  2-pass tf32.  M=128(d) x N=128(4b x 32q),
//   K=256 (16 chunks).  3 smem arrays (Wh, CAh, CAl), 2-stage, 2-CTA/SM.
// ============================================================================
__global__ __launch_bounds__(256, 2) void k3_mma(float* __restrict__ out0) {
    extern __shared__ float smf[];
    const int m0 = blockIdx.x * 128;
    const int b0 = blockIdx.y * 4;
    const int tid = threadIdx.x, wid = tid >> 5, lane = tid & 31;
    const int mw = wid & 3, nw = wid >> 2;
    const int lr = lane >> 2, lc = lane & 3;
    const unsigned smb = smem_u32(smf);

    float acc[2][8][4];
#pragma unroll
    for (int i = 0; i < 2; ++i)
#pragma unroll
        for (int j = 0; j < 8; ++j)
#pragma unroll
            for (int e = 0; e < 4; ++e) acc[i][j][e] = 0.0f;

    auto load_stage = [&](int st, int ch) {
        const int kg = ch * 16;
        const unsigned sb = smb + (st * STAGEF3) * 4;
#pragma unroll
        for (int it = 0; it < 6; ++it) {
            int arr = it >> 1;
            int rem = (it & 1) * 256 + tid;
            int r = rem >> 2, seg = rem & 3;
            unsigned dst = sb + (arr * ARRF + r * STRP + seg * 4) * 4;
            const float* src;
            if (arr == 0)      src = g_Wh  + (size_t)(m0 + r) * 256 + kg + seg * 4;
            else if (arr == 1) src = g_CAh + (size_t)(b0 * 32 + r) * 256 + kg + seg * 4;
            else               src = g_CAl + (size_t)(b0 * 32 + r) * 256 + kg + seg * 4;
            cpa16(dst, src);
        }
    };

    load_stage(0, 0);
    CP_COMMIT();

    for (int ch = 0; ch < 16; ++ch) {
        const int st = ch & 1;
        if (ch + 1 < 16) {
            load_stage(st ^ 1, ch + 1);
            CP_COMMIT();
            CP_WAIT(1);
        } else {
            CP_WAIT(0);
        }
        __syncthreads();
        const float* base = smf + st * STAGEF3;
        const float* sAh = base;
        const float* sBh = base + ARRF;
        const float* sBl = base + 2 * ARRF;
#pragma unroll
        for (int k2 = 0; k2 < 2; ++k2) {
            const int ko = k2 * 8 + lc * 2;
            float2 bh[8], bl[8];
#pragma unroll
            for (int sn = 0; sn < 8; ++sn) {
                int nb = nw * 64 + sn * 8 + lr;
                bh[sn] = *(const float2*)(sBh + nb * STRP + ko);
                bl[sn] = *(const float2*)(sBl + nb * STRP + ko);
            }
            float2 a0[2], a1[2];
#pragma unroll
            for (int sm = 0; sm < 2; ++sm) {
                int rb = mw * 32 + sm * 16 + lr;
                a0[sm] = *(const float2*)(sAh + rb * STRP + ko);
                a1[sm] = *(const float2*)(sAh + (rb + 8) * STRP + ko);
            }
#pragma unroll
            for (int sm = 0; sm < 2; ++sm)
#pragma unroll
                for (int sn = 0; sn < 8; ++sn) {
                    mma_tf32(acc[sm][sn], a0[sm].x, a1[sm].x,
                             a0[sm].y, a1[sm].y, bh[sn].x, bh[sn].y);
                    mma_tf32(acc[sm][sn], a0[sm].x, a1[sm].x,
                             a0[sm].y, a1[sm].y, bl[sn].x, bl[sn].y);
                }
        }
        __syncthreads();
    }

#pragma unroll
    for (int sm = 0; sm < 2; ++sm) {
        int dbase = m0 + mw * 32 + sm * 16 + lr;
#pragma unroll
        for (int sn = 0; sn < 8; ++sn) {
            int n = nw * 64 + sn * 8 + 2 * lc;
            int b = b0 + (n >> 5);
            int q = n & 31;
#pragma unroll
            for (int hf = 0; hf < 2; ++hf) {
                int d   = dbase + 8 * hf;
                int c2i = (d >> 3) & 31;
                int q2  = d >> 8;
                float* o = out0 + ((b * 32 + c2i) * 32 + q2) * 256 + (d & 7) * 32 + q;
                *(float2*)o = make_float2(acc[sm][sn][2 * hf], acc[sm][sn][2 * hf + 1]);
            }
        }
    }
}

// ============================================================================
extern "C" void kernel_launch(void* const* d_in, const int* in_sizes, int n_in,
                              void* d_out, int out_size) {
    const float* inp = (const float*)d_in[0];
    const float* ctx = (const float*)d_in[1];
    const float* W   = (const float*)d_in[2];
    float* out = (float*)d_out;

    static int inited = 0;
    if (!inited) {
        cudaFuncSetAttribute(k1_mma, cudaFuncAttributeMaxDynamicSharedMemorySize, K1_SMEM);
        cudaFuncSetAttribute(k2_attn, cudaFuncAttributeMaxDynamicSharedMemorySize, K2_SMEM);
        cudaFuncSetAttribute(k3_mma, cudaFuncAttributeMaxDynamicSharedMemorySize, SMEM_K3);
        inited = 1;
    }

    k0b_split_W<<<IDF_SZ / 32, 256>>>(W);
    k1_mma<<<dim3(16, KS1), 512, K1_SMEM>>>(inp);
    k2_attn<<<B_SZ * 2, 256, K2_SMEM>>>(ctx, out + WC_ELEMS);
    k3_mma<<<dim3(64, 16), 256, SMEM_K3>>>(out);
}

// round 11
// speedup vs baseline: 2.8250x; 1.2204x over previous
#include <cuda_runtime.h>
#include <cuda_fp16.h>

// Problem:
//   input   [64, 32, 32, 16, 16] f32  -> A rows [b*32+q][d], d = cl*256+hw
//   context [64, 256, 128]       f32
//   W       [8192, 256]          f32
// Outputs: wc [64,32,32,16,16] f32 (16.7M) ; attnT [64,128,32] f32 (262K)
//
// fp16 2-split (h+l), 3 MMA passes (hh, hl, lh), m16n8k16 (fp16 mantissa
// = tf32 mantissa = 11 bits, but 2x the HMMA rate and half the bytes).
// k-dim stored in 16-groups, chunk order {k0,k1,k8,k9|k2,k3,k10,k11|...},
// split into two 16B "subs" per row (sub1 base === 16 mod 32 words) ->
// conflict-free STS.128 staging AND single-LDS.64 fragment loads.

#define B_SZ   64
#define IDF_SZ 8192
#define WC_ELEMS (B_SZ * IDF_SZ * 32)      // 16777216
#define W_ELEMS  (IDF_SZ * 256)
#define KS1    8
#define MROWS  (B_SZ * 32)                 // 2048
#define T2_STRIDE (MROWS * 256)            // 524288

// A-type array (128 rows x 16 fp16): sub0 2048B | pad 64 | sub1 2048B
#define A_SUB  2112
#define A_ARR  4160
// B-type array (256 rows x 16 fp16)
#define B_SUB  4160
#define B_ARR  8256

#define K1_STAGEB (2 * A_ARR + 2 * B_ARR)  // 24832 B
#define K1_SMEM   (3 * K1_STAGEB)          // 74496 B
#define K1_NCH    64

#define K3_STAGEB (4 * A_ARR)              // 16640 B
#define K3_SMEM   (2 * K3_STAGEB)          // 33280 B

#define CPAD  129
#define APAD2 133
#define K2_CTXF  (256 * CPAD)
#define K2_T2F   (16 * 256)
#define K2_ATTNF (16 * APAD2)
#define K2_SMEM  ((K2_CTXF + K2_T2F + K2_ATTNF) * 4)   // 156992 B

// ---------------- device scratch ----------------
__device__ __align__(16) __half g_Wh[W_ELEMS];    // [d][cperm16]
__device__ __align__(16) __half g_Wl[W_ELEMS];
__device__ __align__(16) __half g_WTh[W_ELEMS];   // [c][dperm16]
__device__ __align__(16) __half g_WTl[W_ELEMS];
__device__ float g_T2p[KS1 * T2_STRIDE];          // 16 MB
__device__ __align__(16) __half g_CAh[MROWS * 256];  // [row][cperm16]
__device__ __align__(16) __half g_CAl[MROWS * 256];

// ---------------- helpers ----------------
__device__ __forceinline__ unsigned pk2(float a, float b) {
    __half2 h = __floats2half2_rn(a, b);
    return *reinterpret_cast<unsigned*>(&h);
}
__device__ __forceinline__ void mma_f16(float* c, unsigned a0, unsigned a1,
                                        unsigned a2, unsigned a3,
                                        unsigned b0, unsigned b1) {
    asm volatile(
        "mma.sync.aligned.m16n8k16.row.col.f32.f16.f16.f32 "
        "{%0,%1,%2,%3}, {%4,%5,%6,%7}, {%8,%9}, {%0,%1,%2,%3};"
        : "+f"(c[0]), "+f"(c[1]), "+f"(c[2]), "+f"(c[3])
        : "r"(a0), "r"(a1), "r"(a2), "r"(a3), "r"(b0), "r"(b1));
}
__device__ __forceinline__ unsigned smem_u32(const void* p) {
    unsigned a;
    asm("{ .reg .u64 t; cvta.to.shared.u64 t, %1; cvt.u32.u64 %0, t; }"
        : "=r"(a) : "l"(p));
    return a;
}
__device__ __forceinline__ void cpa16(unsigned dst, const void* src) {
    asm volatile("cp.async.cg.shared.global [%0], [%1], 16;"
                 :: "r"(dst), "l"(src));
}
#define CP_COMMIT() asm volatile("cp.async.commit_group;" ::: "memory")
#define CP_WAIT(N)  asm volatile("cp.async.wait_group %0;" :: "n"(N) : "memory")

// split v[16] (logical k order) into fp16 h/l and write 32B per array in
// chunk order: {v0,v1,v8,v9},{v2,v3,v10,v11},{v4,v5,v12,v13},{v6,v7,v14,v15}
__device__ __forceinline__ void split_g16(const float* v, __half* dh, __half* dl) {
    float h[16], l[16];
#pragma unroll
    for (int e = 0; e < 16; ++e) {
        h[e] = __half2float(__float2half_rn(v[e]));
        l[e] = v[e] - h[e];
    }
    *(uint4*)dh = make_uint4(pk2(h[0], h[1]), pk2(h[8], h[9]),
                             pk2(h[2], h[3]), pk2(h[10], h[11]));
    *(uint4*)(dh + 8) = make_uint4(pk2(h[4], h[5]), pk2(h[12], h[13]),
                                   pk2(h[6], h[7]), pk2(h[14], h[15]));
    *(uint4*)dl = make_uint4(pk2(l[0], l[1]), pk2(l[8], l[9]),
                             pk2(l[2], l[3]), pk2(l[10], l[11]));
    *(uint4*)(dl + 8) = make_uint4(pk2(l[4], l[5]), pk2(l[12], l[13]),
                                   pk2(l[6], l[7]), pk2(l[14], l[15]));
}

// ============================================================================
// k0b: split W -> fp16 native [d][cperm16] and transposed [c][dperm16]
// ============================================================================
__global__ __launch_bounds__(256) void k0b_split_W(const float* __restrict__ W) {
    __shared__ float tw[32 * 260];
    const int d0  = blockIdx.x * 32;
    const int tid = threadIdx.x;
    {
        int row = tid >> 3;
        int c0  = (tid & 7) * 32;
#pragma unroll
        for (int grp = 0; grp < 2; ++grp) {
            int cb = c0 + grp * 16;
            float v[16];
#pragma unroll
            for (int j = 0; j < 4; ++j) {
                float4 t = *(const float4*)(W + (d0 + row) * 256 + cb + 4 * j);
                v[4*j] = t.x; v[4*j+1] = t.y; v[4*j+2] = t.z; v[4*j+3] = t.w;
                *(float4*)(tw + row * 260 + cb + 4 * j) = t;
            }
            split_g16(v, g_Wh + (d0 + row) * 256 + cb,
                         g_Wl + (d0 + row) * 256 + cb);
        }
    }
    __syncthreads();
    {
        int c = tid;
#pragma unroll
        for (int g = 0; g < 2; ++g) {
            float v[16];
#pragma unroll
            for (int i = 0; i < 16; ++i)
                v[i] = tw[(g * 16 + i) * 260 + c];
            split_g16(v, g_WTh + (size_t)c * IDF_SZ + d0 + g * 16,
                         g_WTl + (size_t)c * IDF_SZ + d0 + g * 16);
        }
    }
}

// ============================================================================
// k1: T2 partials. 512 threads, M=128(row) x N=256(c), K=1024/block.
//   Grid (16 mt, 8 ks). 16 warps (2m x 8n). 3-stage cp.async ring.
//   A: raw input LDG (threads 0-127, one full 16-k row each) -> fp16 split
//   -> STS.128.  B: cp.async from pre-split g_WT{h,l}.
// ============================================================================
__global__ __launch_bounds__(512, 1) void k1_mma(const float* __restrict__ inp) {
    extern __shared__ char smc[];
    const int mt = blockIdx.x, ks = blockIdx.y;
    const int m0 = mt * 128, kg0 = ks * 1024;
    const int tid = threadIdx.x, wid = tid >> 5, lane = tid & 31;
    const int mw = wid & 1, nw = wid >> 1;
    const int lr = lane >> 2, lc = lane & 3;
    const unsigned smb = smem_u32(smc);

    float acc[4][4][4];
#pragma unroll
    for (int i = 0; i < 4; ++i)
#pragma unroll
        for (int j = 0; j < 4; ++j)
#pragma unroll
            for (int e = 0; e < 4; ++e) acc[i][j][e] = 0.0f;

    const int arow = tid;                 // valid when tid < 128
    const int aR = m0 + (arow & 127);
    const int ab = aR >> 5, aq = aR & 31;

    auto load_A_regs = [&](int ch, float* xr) {
        if (tid < 128) {
            const int kg = kg0 + ch * 16;
            const int cl = kg >> 8, hw = kg & 255;
            const float* src = inp + (((ab * 32 + cl) * 32 + aq) << 8) + hw;
#pragma unroll
            for (int j = 0; j < 4; ++j) {
                float4 t = *(const float4*)(src + 4 * j);
                xr[4*j] = t.x; xr[4*j+1] = t.y; xr[4*j+2] = t.z; xr[4*j+3] = t.w;
            }
        }
    };
    auto sts_A = [&](int st, const float* xr) {
        if (tid < 128) {
            char* base = smc + st * K1_STAGEB + arow * 16;
            float h[16], l[16];
#pragma unroll
            for (int e = 0; e < 16; ++e) {
                h[e] = __half2float(__float2half_rn(xr[e]));
                l[e] = xr[e] - h[e];
            }
            *(uint4*)(base) = make_uint4(pk2(h[0],h[1]), pk2(h[8],h[9]),
                                         pk2(h[2],h[3]), pk2(h[10],h[11]));
            *(uint4*)(base + A_SUB) = make_uint4(pk2(h[4],h[5]), pk2(h[12],h[13]),
                                                 pk2(h[6],h[7]), pk2(h[14],h[15]));
            *(uint4*)(base + A_ARR) = make_uint4(pk2(l[0],l[1]), pk2(l[8],l[9]),
                                                 pk2(l[2],l[3]), pk2(l[10],l[11]));
            *(uint4*)(base + A_ARR + A_SUB) = make_uint4(pk2(l[4],l[5]), pk2(l[12],l[13]),
                                                         pk2(l[6],l[7]), pk2(l[14],l[15]));
        }
    };
    auto load_B = [&](int st, int ch) {
        const int kg = kg0 + ch * 16;
        const unsigned sb = smb + st * K1_STAGEB + 2 * A_ARR;
#pragma unroll
        for (int it = 0; it < 2; ++it) {
            int idx = it * 512 + tid;            // 0..1023
            int arr = idx >> 9, rem = idx & 511;
            int n = rem >> 1, sub = rem & 1;
            unsigned dst = sb + arr * B_ARR + sub * B_SUB + n * 16;
            const __half* src = (arr ? g_WTl : g_WTh) + (size_t)n * IDF_SZ + kg + sub * 8;
            cpa16(dst, src);
        }
    };

    float xr[16];
    load_A_regs(0, xr);
    sts_A(0, xr);
    load_A_regs(1, xr);
    load_B(0, 0); CP_COMMIT();
    load_B(1, 1); CP_COMMIT();

    const int aoff = (lc >> 1) * A_SUB + (lc & 1) * 8;
    const int boff = (lc >> 1) * B_SUB + (lc & 1) * 8;

    for (int ch = 0; ch < K1_NCH; ++ch) {
        const int st = ch % 3;
        CP_WAIT(1);
        __syncthreads();
        if (ch + 1 < K1_NCH) sts_A((ch + 1) % 3, xr);
        if (ch + 2 < K1_NCH) {
            load_A_regs(ch + 2, xr);
            load_B((ch + 2) % 3, ch + 2);
        }
        CP_COMMIT();

        const char* base = smc + st * K1_STAGEB;
        const char* pAh = base;
        const char* pAl = base + A_ARR;
        const char* pBh = base + 2 * A_ARR;
        const char* pBl = base + 2 * A_ARR + B_ARR;

        uint2 bh[4], bl[4];
#pragma unroll
        for (int sn = 0; sn < 4; ++sn) {
            int nb = nw * 32 + sn * 8 + lr;
            bh[sn] = *(const uint2*)(pBh + boff + nb * 16);
            bl[sn] = *(const uint2*)(pBl + boff + nb * 16);
        }
        {
            uint2 alo[4], ahi[4];
#pragma unroll
            for (int sm = 0; sm < 4; ++sm) {
                int rb = mw * 64 + sm * 16 + lr;
                alo[sm] = *(const uint2*)(pAh + aoff + rb * 16);
                ahi[sm] = *(const uint2*)(pAh + aoff + (rb + 8) * 16);
            }
#pragma unroll
            for (int sm = 0; sm < 4; ++sm)
#pragma unroll
                for (int sn = 0; sn < 4; ++sn) {
                    mma_f16(acc[sm][sn], alo[sm].x, ahi[sm].x, alo[sm].y, ahi[sm].y,
                            bh[sn].x, bh[sn].y);
                    mma_f16(acc[sm][sn], alo[sm].x, ahi[sm].x, alo[sm].y, ahi[sm].y,
                            bl[sn].x, bl[sn].y);
                }
        }
        {
            uint2 alo[4], ahi[4];
#pragma unroll
            for (int sm = 0; sm < 4; ++sm) {
                int rb = mw * 64 + sm * 16 + lr;
                alo[sm] = *(const uint2*)(pAl + aoff + rb * 16);
                ahi[sm] = *(const uint2*)(pAl + aoff + (rb + 8) * 16);
            }
#pragma unroll
            for (int sm = 0; sm < 4; ++sm)
#pragma unroll
                for (int sn = 0; sn < 4; ++sn)
                    mma_f16(acc[sm][sn], alo[sm].x, ahi[sm].x, alo[sm].y, ahi[sm].y,
                            bh[sn].x, bh[sn].y);
        }
        __syncthreads();
    }

    float* dst = g_T2p + (size_t)ks * T2_STRIDE;
#pragma unroll
    for (int sm = 0; sm < 4; ++sm) {
        int r = m0 + mw * 64 + sm * 16 + lr;
#pragma unroll
        for (int sn = 0; sn < 4; ++sn) {
            int c = nw * 32 + sn * 8 + 2 * lc;
            *(float2*)(dst + r * 256 + c) = make_float2(acc[sm][sn][0], acc[sm][sn][1]);
            *(float2*)(dst + (r + 8) * 256 + c) = make_float2(acc[sm][sn][2], acc[sm][sn][3]);
        }
    }
}

// ============================================================================
// k2 (2 blocks per b, 16 q-rows each, 256 threads): smem-staged ctx.
//   CA output -> fp16 h/l with perm16 along c.
// ============================================================================
__global__ __launch_bounds__(256) void k2_attn(const float* __restrict__ ctx,
                                               float* __restrict__ outAttnT) {
    extern __shared__ float s2[];
    float* ctxs = s2;
    float* T2s  = s2 + K2_CTXF;
    float* attn = T2s + K2_T2F;

    const int b   = blockIdx.x >> 1;
    const int q0  = (blockIdx.x & 1) * 16;
    const int tid = threadIdx.x;

    {
        const float* cb = ctx + b * 32768;
#pragma unroll
        for (int i = 0; i < 32; ++i) {
            int idx = tid + i * 256;
            int c = idx >> 5, s4 = (idx & 31) * 4;
            float4 v = *(const float4*)(cb + c * 128 + s4);
            float* d = ctxs + c * CPAD + s4;
            d[0] = v.x; d[1] = v.y; d[2] = v.z; d[3] = v.w;
        }
    }
#pragma unroll
    for (int i = 0; i < 4; ++i) {
        int idx = tid + i * 256;
        int ql  = idx >> 6;
        int cc  = (idx & 63) * 4;
        const float* src = g_T2p + (b * 32 + q0 + ql) * 256 + cc;
        float4 s = *(const float4*)(src);
#pragma unroll
        for (int p = 1; p < KS1; ++p) {
            float4 t = *(const float4*)(src + (size_t)p * T2_STRIDE);
            s.x += t.x; s.y += t.y; s.z += t.z; s.w += t.w;
        }
        *(float4*)(T2s + ql * 256 + cc) = s;
    }
    __syncthreads();

    {
        const int s = tid & 127;
        const int g = tid >> 7;
        float acc[8];
#pragma unroll
        for (int j = 0; j < 8; ++j) acc[j] = 0.0f;
        const float* t2 = T2s + g * 8 * 256;
        for (int c = 0; c < 256; ++c) {
            float cv = ctxs[c * CPAD + s];
#pragma unroll
            for (int j = 0; j < 8; ++j)
                acc[j] += t2[j * 256 + c] * cv;
        }
#pragma unroll
        for (int j = 0; j < 8; ++j) attn[(g * 8 + j) * APAD2 + s] = acc[j];
    }
    __syncthreads();

    {
        const int warp = tid >> 5, lane = tid & 31;
#pragma unroll
        for (int r = 0; r < 2; ++r) {
            int q = warp * 2 + r;
            float v0 = attn[q * APAD2 + lane];
            float v1 = attn[q * APAD2 + lane + 32];
            float v2 = attn[q * APAD2 + lane + 64];
            float v3 = attn[q * APAD2 + lane + 96];
            float mx = fmaxf(fmaxf(v0, v1), fmaxf(v2, v3));
#pragma unroll
            for (int o = 16; o > 0; o >>= 1)
                mx = fmaxf(mx, __shfl_xor_sync(0xffffffffu, mx, o));
            float e0 = expf(v0 - mx), e1 = expf(v1 - mx);
            float e2 = expf(v2 - mx), e3 = expf(v3 - mx);
            float sm = e0 + e1 + e2 + e3;
#pragma unroll
            for (int o = 16; o > 0; o >>= 1)
                sm += __shfl_xor_sync(0xffffffffu, sm, o);
            float inv = 1.0f / sm;
            attn[q * APAD2 + lane]      = e0 * inv;
            attn[q * APAD2 + lane + 32] = e1 * inv;
            attn[q * APAD2 + lane + 64] = e2 * inv;
            attn[q * APAD2 + lane + 96] = e3 * inv;
        }
    }
    __syncthreads();

#pragma unroll
    for (int i = 0; i < 8; ++i) {
        int idx = tid + i * 256;
        int s = idx >> 4, ql = idx & 15;
        outAttnT[b * 4096 + s * 32 + q0 + ql] = attn[ql * APAD2 + s];
    }

    {
        const int c = tid;
        float a2[16];
#pragma unroll
        for (int j = 0; j < 16; ++j) a2[j] = 0.0f;
        const float* cr = ctxs + c * CPAD;
        for (int s = 0; s < 128; ++s) {
            float cv = cr[s];
#pragma unroll
            for (int j = 0; j < 16; ++j)
                a2[j] += attn[j * APAD2 + s] * cv;
        }
        int jj = c & 15;
        int cpos = (c & ~15) | ((jj & 1) | (((jj >> 1) & 3) << 2) | (((jj >> 3) & 1) << 1));
#pragma unroll
        for (int j = 0; j < 16; ++j) {
            __half h = __float2half_rn(a2[j]);
            float l = a2[j] - __half2float(h);
            int gi = (b * 32 + q0 + j) * 256 + cpos;
            g_CAh[gi] = h;
            g_CAl[gi] = __float2half_rn(l);
        }
    }
}

// ============================================================================
// k3: wc = W @ CA^T, fp16 3-pass (hh, hl, lh).  M=128(d) x N=128(4b x 32q),
//   K=256 (16 chunks). 4 A-type arrays, 2-stage, 2-CTA/SM.
// ============================================================================
__global__ __launch_bounds__(256, 2) void k3_mma(float* __restrict__ out0) {
    extern __shared__ char smc[];
    const int m0 = blockIdx.x * 128;
    const int b0 = blockIdx.y * 4;
    const int tid = threadIdx.x, wid = tid >> 5, lane = tid & 31;
    const int mw = wid & 3, nw = wid >> 2;
    const int lr = lane >> 2, lc = lane & 3;
    const unsigned smb = smem_u32(smc);

    float acc[2][8][4];
#pragma unroll
    for (int i = 0; i < 2; ++i)
#pragma unroll
        for (int j = 0; j < 8; ++j)
#pragma unroll
            for (int e = 0; e < 4; ++e) acc[i][j][e] = 0.0f;

    auto load_stage = [&](int st, int ch) {
        const int kg = ch * 16;
        const unsigned sb = smb + st * K3_STAGEB;
#pragma unroll
        for (int it = 0; it < 4; ++it) {
            int idx = it * 256 + tid;            // 0..1023
            int arr = idx >> 8, rem = idx & 255;
            int r = rem >> 1, sub = rem & 1;
            unsigned dst = sb + arr * A_ARR + sub * A_SUB + r * 16;
            const __half* src;
            if (arr == 0)      src = g_Wh  + (size_t)(m0 + r) * 256 + kg + sub * 8;
            else if (arr == 1) src = g_Wl  + (size_t)(m0 + r) * 256 + kg + sub * 8;
            else if (arr == 2) src = g_CAh + (size_t)(b0 * 32 + r) * 256 + kg + sub * 8;
            else               src = g_CAl + (size_t)(b0 * 32 + r) * 256 + kg + sub * 8;
            cpa16(dst, src);
        }
    };

    load_stage(0, 0);
    CP_COMMIT();

    const int aoff = (lc >> 1) * A_SUB + (lc & 1) * 8;

    for (int ch = 0; ch < 16; ++ch) {
        const int st = ch & 1;
        if (ch + 1 < 16) {
            load_stage(st ^ 1, ch + 1);
            CP_COMMIT();
            CP_WAIT(1);
        } else {
            CP_WAIT(0);
        }
        __syncthreads();
        const char* base = smc + st * K3_STAGEB;
        const char* pAh = base;
        const char* pAl = base + A_ARR;
        const char* pBh = base + 2 * A_ARR;
        const char* pBl = base + 3 * A_ARR;

        uint2 bh[8], bl[8];
#pragma unroll
        for (int sn = 0; sn < 8; ++sn) {
            int nb = nw * 64 + sn * 8 + lr;
            bh[sn] = *(const uint2*)(pBh + aoff + nb * 16);
            bl[sn] = *(const uint2*)(pBl + aoff + nb * 16);
        }
        {
            uint2 alo[2], ahi[2];
#pragma unroll
            for (int sm = 0; sm < 2; ++sm) {
                int rb = mw * 32 + sm * 16 + lr;
                alo[sm] = *(const uint2*)(pAh + aoff + rb * 16);
                ahi[sm] = *(const uint2*)(pAh + aoff + (rb + 8) * 16);
            }
#pragma unroll
            for (int sm = 0; sm < 2; ++sm)
#pragma unroll
                for (int sn = 0; sn < 8; ++sn) {
                    mma_f16(acc[sm][sn], alo[sm].x, ahi[sm].x, alo[sm].y, ahi[sm].y,
                            bh[sn].x, bh[sn].y);
                    mma_f16(acc[sm][sn], alo[sm].x, ahi[sm].x, alo[sm].y, ahi[sm].y,
                            bl[sn].x, bl[sn].y);
                }
        }
        {
            uint2 alo[2], ahi[2];
#pragma unroll
            for (int sm = 0; sm < 2; ++sm) {
                int rb = mw * 32 + sm * 16 + lr;
                alo[sm] = *(const uint2*)(pAl + aoff + rb * 16);
                ahi[sm] = *(const uint2*)(pAl + aoff + (rb + 8) * 16);
            }
#pragma unroll
            for (int sm = 0; sm < 2; ++sm)
#pragma unroll
                for (int sn = 0; sn < 8; ++sn)
                    mma_f16(acc[sm][sn], alo[sm].x, ahi[sm].x, alo[sm].y, ahi[sm].y,
                            bh[sn].x, bh[sn].y);
        }
        __syncthreads();
    }

#pragma unroll
    for (int sm = 0; sm < 2; ++sm) {
        int dbase = m0 + mw * 32 + sm * 16 + lr;
#pragma unroll
        for (int sn = 0; sn < 8; ++sn) {
            int n = nw * 64 + sn * 8 + 2 * lc;
            int b = b0 + (n >> 5);
            int q = n & 31;
#pragma unroll
            for (int hf = 0; hf < 2; ++hf) {
                int d   = dbase + 8 * hf;
                int c2i = (d >> 3) & 31;
                int q2  = d >> 8;
                float* o = out0 + ((b * 32 + c2i) * 32 + q2) * 256 + (d & 7) * 32 + q;
                *(float2*)o = make_float2(acc[sm][sn][2 * hf], acc[sm][sn][2 * hf + 1]);
            }
        }
    }
}

// ============================================================================
extern "C" void kernel_launch(void* const* d_in, const int* in_sizes, int n_in,
                              void* d_out, int out_size) {
    const float* inp = (const float*)d_in[0];
    const float* ctx = (const float*)d_in[1];
    const float* W   = (const float*)d_in[2];
    float* out = (float*)d_out;

    static int inited = 0;
    if (!inited) {
        cudaFuncSetAttribute(k1_mma, cudaFuncAttributeMaxDynamicSharedMemorySize, K1_SMEM);
        cudaFuncSetAttribute(k2_attn, cudaFuncAttributeMaxDynamicSharedMemorySize, K2_SMEM);
        cudaFuncSetAttribute(k3_mma, cudaFuncAttributeMaxDynamicSharedMemorySize, K3_SMEM);
        inited = 1;
    }

    k0b_split_W<<<IDF_SZ / 32, 256>>>(W);
    k1_mma<<<dim3(16, KS1), 512, K1_SMEM>>>(inp);
    k2_attn<<<B_SZ * 2, 256, K2_SMEM>>>(ctx, out + WC_ELEMS);
    k3_mma<<<dim3(64, 16), 256, K3_SMEM>>>(out);
}